// round 13
// baseline (speedup 1.0000x reference)
#include <cuda_runtime.h>
#include <math.h>
#include <stdint.h>

#define NTHREADS 256
#define PAIRS    16
#define ROWS     48
#define NBLK     2048

typedef unsigned long long ull;

// smem map (floats), total 12480 = 49920 B -> 4 blocks/SM:
//  R0 [0,8256):  evt 48x172 (=8256)  ->  GH1 [0,3072) + GH2 [3072,6144)
//                -> feat 48x128 [0,6144)  |  Wp/outb/xb/h2b at [6144,8256)
//  R1 [8256,12480): Abuf 2x2112 (=4224) | WQ 32x128 + scb | hb/sf/h1b
#define R0_OFF 0
#define R1_OFF 8256
#define SMEM_FLOATS 12480
#define SMEM_BYTES (SMEM_FLOATS*4)
// R0 aliases
#define GH1_O   0        // 48x64 = 3072 (overlays dead evt)
#define GH2_O   3072     // 48x64 = 3072
#define WP_O    6144     // 16x128 = 2048
#define OUTB_O  6144     // over Wp (dead)
#define XB_O    6144     // over outb (dead)
#define H2B_O   6144     // over xb (dead)
// R1 aliases
#define WQ_O    0        // 32x128 = 4096
#define SCB_O   4096     // 32 floats
#define HB_O    0        // 16x64 = 1024
#define SF_O    1024     // 16x64
#define H1B_O   2048     // 16x76 = 1216

__device__ __forceinline__ ull pack2(float lo, float hi) {
    ull r; asm("mov.b64 %0, {%1, %2};" : "=l"(r) : "f"(lo), "f"(hi)); return r;
}
__device__ __forceinline__ void unpack2(ull v, float& lo, float& hi) {
    asm("mov.b64 {%0, %1}, %2;" : "=f"(lo), "=f"(hi) : "l"(v));
}
__device__ __forceinline__ void fma2(ull& d, ull a, ull b) {
    asm("fma.rn.f32x2 %0, %1, %2, %0;" : "+l"(d) : "l"(a), "l"(b));
}
__device__ __forceinline__ float fsel4(float4 v, int kk) {
    return (kk==0)?v.x:(kk==1)?v.y:(kk==2)?v.z:v.w;
}

// ---------------------------------------------------------------------------
// Pre-transposed / padded weights ([k][o] layout, zero padded)
// ---------------------------------------------------------------------------
__device__ __align__(16) float g_WT_event[352*192];
__device__ __align__(16) float g_WT_gcn1 [176*64];
__device__ __align__(16) float g_WT_gcn2 [ 64*64];
__device__ __align__(16) float g_WT_att1 [128*128];
__device__ __align__(16) float g_WT_att2 [128*128];
__device__ __align__(16) float g_WT_m1   [128*64];
__device__ __align__(16) float g_WT_m2   [ 64*64];
__device__ __align__(16) float g_WT_mlp1 [76*128];
__device__ __align__(16) float g_WT_mlp2 [76*64];
__device__ __align__(16) float g_ct2     [192];

__global__ void prep_kernel(const float* __restrict__ ew,
                            const float* __restrict__ g1,
                            const float* __restrict__ g2,
                            const float* __restrict__ a1,
                            const float* __restrict__ a2,
                            const float* __restrict__ m1,
                            const float* __restrict__ m2,
                            const float* __restrict__ w1,
                            const float* __restrict__ w2,
                            const float* __restrict__ ph)
{
    int t0 = blockIdx.x*blockDim.x + threadIdx.x;
    int stride = gridDim.x*blockDim.x;
    for (int i = t0; i < 352*192; i += stride) {
        int k = i/192, o = i%192;
        g_WT_event[i] = (k < 347 && o < 172) ? ew[o*347 + k] : 0.f;
    }
    for (int i = t0; i < 176*64; i += stride) {
        int k = i/64, o = i%64;
        g_WT_gcn1[i] = (k < 172) ? g1[o*172 + k] : 0.f;
    }
    for (int i = t0; i < 64*64; i += stride) {
        int k = i/64, o = i%64;
        g_WT_gcn2[i] = g2[o*64 + k];
        g_WT_m2[i]   = m2[o*64 + k];
    }
    for (int i = t0; i < 128*128; i += stride) {
        int k = i/128, o = i%128;
        g_WT_att1[i] = a1[o*128 + k];
        g_WT_att2[i] = a2[o*128 + k];
    }
    for (int i = t0; i < 128*64; i += stride) {
        int k = i/64, o = i%64;
        g_WT_m1[i] = m1[o*128 + k];
    }
    for (int i = t0; i < 76*128; i += stride) {
        int k = i/128, o = i%128;
        g_WT_mlp1[i] = (o < 76) ? w1[o*76 + k] : 0.f;
    }
    for (int i = t0; i < 76*64; i += stride) {
        int k = i/64, o = i%64;
        g_WT_mlp2[i] = w2[o*76 + k];
    }
    for (int o = t0; o < 192; o += stride) {
        float s = 0.f;
        if (o < 172) {
            for (int d = 1; d < 172; d++)
                s += cosf(ph[d]) * ew[o*347 + 175 + d];
        }
        g_ct2[o] = s;
    }
}

// ---------------------------------------------------------------------------
// Row-pointer maps for GEMM A operands
// ---------------------------------------------------------------------------
struct PitchMap {
    const float* base; int sa;
    __device__ __forceinline__ const float* operator()(int r) const { return base + r*sa; }
};
struct TgtMap {   // attention K/V rows: r -> feat row (r>>1)*3 + (r&1)
    const float* feat;
    __device__ __forceinline__ const float* operator()(int r) const {
        return feat + ((r >> 1)*3 + (r & 1))*128;
    }
};
struct SrcMap {   // attention Q rows: p -> feat row 3p+2
    const float* feat;
    __device__ __forceinline__ const float* operator()(int r) const {
        return feat + (r*3 + 2)*128;
    }
};

// ---------------------------------------------------------------------------
// Direct GEMM with A row-map. 8 warps; thread (ty,tx): rows [ty*RT,..+RT),
// cols {g*64+2tx,+1}, g<P. Weights batched 4 k's up-front.
// ---------------------------------------------------------------------------
template<int NS, int K, int RT, int P, bool RELU, int NREAL, typename AMap>
__device__ __forceinline__ void gemm_direct(
    const float* __restrict__ Wg, const float* __restrict__ bias,
    const AMap& amap,
    float* __restrict__ C, int sc, int tid)
{
    const int ty = tid >> 5, tx = tid & 31;
    ull acc[RT][P];
#pragma unroll
    for (int i = 0; i < RT; i++)
#pragma unroll
        for (int g = 0; g < P; g++) acc[i][g] = 0ull;
    const float* wq = Wg + 2*tx;
    const float* ar[RT];
#pragma unroll
    for (int i = 0; i < RT; i++) ar[i] = amap(ty*RT + i);
#pragma unroll 1
    for (int k4 = 0; k4 < K; k4 += 4) {
        ull w[4][P];
#pragma unroll
        for (int kk = 0; kk < 4; kk++)
#pragma unroll
            for (int g = 0; g < P; g++)
                w[kk][g] = __ldg(reinterpret_cast<const ull*>(wq + (k4+kk)*NS + g*64));
        float4 av[RT];
#pragma unroll
        for (int i = 0; i < RT; i++)
            av[i] = *reinterpret_cast<const float4*>(ar[i] + k4);
#pragma unroll
        for (int kk = 0; kk < 4; kk++)
#pragma unroll
            for (int i = 0; i < RT; i++) {
                float a = fsel4(av[i], kk);
                ull ad = pack2(a, a);
#pragma unroll
                for (int g = 0; g < P; g++) fma2(acc[i][g], ad, w[kk][g]);
            }
    }
#pragma unroll
    for (int i = 0; i < RT; i++)
#pragma unroll
        for (int g = 0; g < P; g++) {
            int col = g*64 + 2*tx;
            float x, y; unpack2(acc[i][g], x, y);
            int row = ty*RT + i;
            if (col < NREAL) {
                float v = x + __ldg(&bias[col]);
                if (RELU) v = fmaxf(v, 0.f);
                C[row*sc + col] = v;
            }
            if (col + 1 < NREAL) {
                float v = y + __ldg(&bias[col+1]);
                if (RELU) v = fmaxf(v, 0.f);
                C[row*sc + col + 1] = v;
            }
        }
    __syncthreads();
}

// ---------------------------------------------------------------------------
// Event generators
// ---------------------------------------------------------------------------
struct EventGenA {          // cols [0,176), 48 rows
    const int*   edge_idx;
    const float* edge_embed;
    const float* edge_identify;
    const float* t_records;
    const float* basis_freq;
    const float* phase;
    int g0;
    __device__ __forceinline__ void operator()(float* Abuf, int kc, int tid) const {
        for (int idx = tid; idx < ROWS*44; idx += NTHREADS) {
            int r = idx / 44, cc = idx - r*44;
            int c = kc + cc;
            int p = r / 3, l = r - p*3;
            int g = g0 + p;
            float v = 0.f;
            if (c < 172) {
                int e = __ldg(&edge_idx[g*3 + l]);
                v = __ldg(&edge_embed[(long)e*172 + c]);
            } else if (c < 175) {
                v = __ldg(&edge_identify[(g*3 + l)*3 + (c - 172)]);
            } else if (c == 175) {
                float dt = __ldg(&t_records[g*3 + 2]) - __ldg(&t_records[g*3 + l]);
                v = __cosf(dt * __ldg(&basis_freq[0]) + __ldg(&phase[0]));
            }
            Abuf[idx] = v;
        }
    }
};
struct EventGenB {          // cols 176+kc.., 32 rows (l != 2)
    const float* t_records;
    const float* basis_freq;
    const float* phase;
    int g0;
    __device__ __forceinline__ void operator()(float* Abuf, int kc, int tid) const {
        for (int idx = tid; idx < 32*44; idx += NTHREADS) {
            int rr = idx / 44, cc = idx - rr*44;
            int c = 176 + kc + cc;
            int p = rr >> 1, l = rr & 1;
            int g = g0 + p;
            float v = 0.f;
            if (c < 347) {
                int d = c - 175;
                float dt = __ldg(&t_records[g*3 + 2]) - __ldg(&t_records[g*3 + l]);
                v = __cosf(dt * __ldg(&basis_freq[d]) + __ldg(&phase[d]));
            }
            Abuf[idx] = v;
        }
    }
};
struct IdMap   { __device__ __forceinline__ int operator()(int r) const { return r; } };
struct TriMap2 { __device__ __forceinline__ int operator()(int rr) const { return (rr>>1)*3 + (rr&1); } };

// ---------------------------------------------------------------------------
// Event column-pass: K=176 (4 chunks of 44), double-buffered gen. P<=2.
// ---------------------------------------------------------------------------
template<int RT, int MR, int P, bool ACC, typename Gen, typename OMap>
__device__ __forceinline__ void event_pass(
    int kbase, int ncol0, const float* __restrict__ bias,
    float* __restrict__ Abuf, const Gen& gen, const OMap& omap,
    float* __restrict__ evt, int tid)
{
    const int ty = tid >> 5, tx = tid & 31;
    ull acc[RT][P];
#pragma unroll
    for (int i = 0; i < RT; i++)
#pragma unroll
        for (int g = 0; g < P; g++) acc[i][g] = 0ull;

    gen(Abuf, 0, tid);
    __syncthreads();
#pragma unroll 1
    for (int kc = 0; kc < 176; kc += 44) {
        int buf = (kc / 44) & 1;
        const float* cur = Abuf + buf*(MR*44);
        if (kc + 44 < 176) gen(Abuf + (buf^1)*(MR*44), kc + 44, tid);
        const float* wq   = g_WT_event + (kbase + kc)*192 + ncol0 + 2*tx;
        const float* arow = cur + ty*RT*44;
#pragma unroll 1
        for (int k4 = 0; k4 < 44; k4 += 4) {
            float4 av[RT];
#pragma unroll
            for (int i = 0; i < RT; i++)
                av[i] = *reinterpret_cast<const float4*>(arow + i*44 + k4);
#pragma unroll
            for (int kk = 0; kk < 4; kk++) {
                ull w[P];
#pragma unroll
                for (int g = 0; g < P; g++)
                    w[g] = __ldg(reinterpret_cast<const ull*>(wq + (k4+kk)*192 + g*64));
#pragma unroll
                for (int i = 0; i < RT; i++) {
                    float a = fsel4(av[i], kk);
                    ull ad = pack2(a, a);
#pragma unroll
                    for (int g = 0; g < P; g++) fma2(acc[i][g], ad, w[g]);
                }
            }
        }
        __syncthreads();
    }
#pragma unroll
    for (int i = 0; i < RT; i++)
#pragma unroll
        for (int g = 0; g < P; g++) {
            int col = ncol0 + g*64 + 2*tx;
            float x, y; unpack2(acc[i][g], x, y);
            int row = omap(ty*RT + i);
            if (col < 172) {
                if (ACC) evt[row*172 + col] += x;
                else     evt[row*172 + col]  = x + __ldg(&bias[col]);
            }
            if (col + 1 < 172) {
                if (ACC) evt[row*172 + col + 1] += y;
                else     evt[row*172 + col + 1]  = y + __ldg(&bias[col+1]);
            }
        }
}

// ---------------------------------------------------------------------------
// Dual gine: evt (pitch 172) consumed by gen; GH1/GH2 written into the evt
// region AFTER the final gen's barrier (evt dead by then).
// ---------------------------------------------------------------------------
struct GineDualGen {
    const int*   node_idx;
    const float* node_embed;
    const float* evt;   // smem, pitch 172
    int g0;
    __device__ __forceinline__ void operator()(float* Abuf, int kc, int tid) const {
        for (int idx = tid; idx < ROWS*44; idx += NTHREADS) {
            int r = idx / 44, cc = idx - r*44;
            int c = kc + cc;
            int p = r / 3, l = r - p*3;
            int g = g0 + p;
            float v1 = 0.f, v2 = 0.f;
            if (c < 172) {
                int ns = __ldg(&node_idx[g*6 + 2*l]);
                int nt = __ldg(&node_idx[g*6 + 2*l + 1]);
                float s = __ldg(&node_embed[(long)ns*172 + c]);
                float t = __ldg(&node_embed[(long)nt*172 + c]);
                float e = evt[r*172 + c];
                v1 = s + fmaxf(t + e, 0.f);
                v2 = t + fmaxf(s + e, 0.f);
            }
            Abuf[idx]        = v1;
            Abuf[2112 + idx] = v2;
        }
    }
};

__device__ __forceinline__ void gemm_gine_dual(
    const float* __restrict__ bias,
    float* __restrict__ Abuf, const GineDualGen& gen,
    float* __restrict__ C1, float* __restrict__ C2, int tid)
{
    const int ty = tid >> 5, tx = tid & 31;
    ull acc1[6], acc2[6];
#pragma unroll
    for (int i = 0; i < 6; i++) { acc1[i] = 0ull; acc2[i] = 0ull; }
#pragma unroll 1
    for (int kc = 0; kc < 176; kc += 44) {
        __syncthreads();
        gen(Abuf, kc, tid);
        __syncthreads();
        const float* wq = g_WT_gcn1 + kc*64 + 2*tx;
        const float* a1row = Abuf + ty*6*44;
        const float* a2row = Abuf + 2112 + ty*6*44;
#pragma unroll 1
        for (int k4 = 0; k4 < 44; k4 += 4) {
            ull w[4];
#pragma unroll
            for (int kk = 0; kk < 4; kk++)
                w[kk] = __ldg(reinterpret_cast<const ull*>(wq + (k4+kk)*64));
#pragma unroll
            for (int i = 0; i < 6; i++) {
                float4 a1 = *reinterpret_cast<const float4*>(a1row + i*44 + k4);
                float4 a2 = *reinterpret_cast<const float4*>(a2row + i*44 + k4);
#pragma unroll
                for (int kk = 0; kk < 4; kk++) {
                    fma2(acc1[i], pack2(fsel4(a1,kk), fsel4(a1,kk)), w[kk]);
                    fma2(acc2[i], pack2(fsel4(a2,kk), fsel4(a2,kk)), w[kk]);
                }
            }
        }
    }
    // evt reads are all behind the last post-gen barrier; safe to overwrite
    // the evt region with GH1/GH2 now.
    int col = 2*tx;
    float b0 = __ldg(&bias[col]), b1 = __ldg(&bias[col+1]);
#pragma unroll
    for (int i = 0; i < 6; i++) {
        int row = ty*6 + i;
        float x, y;
        unpack2(acc1[i], x, y);
        C1[row*64 + col]     = fmaxf(x + b0, 0.f);
        C1[row*64 + col + 1] = fmaxf(y + b1, 0.f);
        unpack2(acc2[i], x, y);
        C2[row*64 + col]     = fmaxf(x + b0, 0.f);
        C2[row*64 + col + 1] = fmaxf(y + b1, 0.f);
    }
    __syncthreads();
}

// Dual gcn2: reads H1/H2 fully into accumulators, barrier, then writes feat
// OVER the H region (overlay is safe because of the barrier).
__device__ __forceinline__ void gemm_gcn2_dual(
    const float* __restrict__ bias,
    const float* __restrict__ H1, const float* __restrict__ H2,
    float* __restrict__ feat, int tid)
{
    const int ty = tid >> 5, tx = tid & 31;
    ull acc1[6], acc2[6];
#pragma unroll
    for (int i = 0; i < 6; i++) { acc1[i] = 0ull; acc2[i] = 0ull; }
    const float* wq = g_WT_gcn2 + 2*tx;
#pragma unroll 1
    for (int k4 = 0; k4 < 64; k4 += 4) {
        ull w[4];
#pragma unroll
        for (int kk = 0; kk < 4; kk++)
            w[kk] = __ldg(reinterpret_cast<const ull*>(wq + (k4+kk)*64));
#pragma unroll
        for (int i = 0; i < 6; i++) {
            float4 a1 = *reinterpret_cast<const float4*>(H1 + (ty*6+i)*64 + k4);
            float4 a2 = *reinterpret_cast<const float4*>(H2 + (ty*6+i)*64 + k4);
#pragma unroll
            for (int kk = 0; kk < 4; kk++) {
                fma2(acc1[i], pack2(fsel4(a1,kk), fsel4(a1,kk)), w[kk]);
                fma2(acc2[i], pack2(fsel4(a2,kk), fsel4(a2,kk)), w[kk]);
            }
        }
    }
    __syncthreads();   // ALL H reads complete before feat overwrites H region
    int col = 2*tx;
    float b0 = __ldg(&bias[col]), b1 = __ldg(&bias[col+1]);
#pragma unroll
    for (int i = 0; i < 6; i++) {
        int row = ty*6 + i;
        float x, y;
        unpack2(acc1[i], x, y);
        feat[row*128 + col]      = x + b0;
        feat[row*128 + col + 1]  = y + b1;
        unpack2(acc2[i], x, y);
        feat[row*128 + 64 + col]     = x + b0;
        feat[row*128 + 64 + col + 1] = y + b1;
    }
    __syncthreads();
}

// ---------------------------------------------------------------------------
// Fused main kernel (4 blocks/SM)
// ---------------------------------------------------------------------------
__global__ void __launch_bounds__(NTHREADS, 4)
fused_kernel(const int*   __restrict__ node_idx,
             const int*   __restrict__ edge_idx,
             const int*   __restrict__ cat_feat,
             const float* __restrict__ t_records,
             const float* __restrict__ edge_identify,
             const float* __restrict__ node_embed,
             const float* __restrict__ edge_embed,
             const float* __restrict__ basis_freq,
             const float* __restrict__ phase,
             const float* __restrict__ lin_event_b,
             const float* __restrict__ gcn_b1,
             const float* __restrict__ gcn_b2,
             const float* __restrict__ att_w1_b,
             const float* __restrict__ att_w2_b,
             const float* __restrict__ att_m1_b,
             const float* __restrict__ att_m2_b,
             const float* __restrict__ mlp_b1,
             const float* __restrict__ mlp_b2,
             const float* __restrict__ mlp_w3,
             const float* __restrict__ mlp_b3,
             float*       __restrict__ out)
{
    extern __shared__ float sm[];
    const int tid = threadIdx.x;
    const int g0  = blockIdx.x * PAIRS;

    float* evt  = sm + R0_OFF;          // pitch 172
    float* feat = sm + R0_OFF;          // pitch 128 (after GH dead)
    float* Abuf = sm + R1_OFF;

    // ---- Phase 1: event linear (column passes, P<=2) ----
    EventGenA ega{edge_idx, edge_embed, edge_identify, t_records, basis_freq, phase, g0};
    EventGenB egb{t_records, basis_freq, phase, g0};
    IdMap idm; TriMap2 trm;
    event_pass<6,48,2,false>(0,   0,   lin_event_b, Abuf, ega, idm, evt, tid);
    event_pass<6,48,1,false>(0,   128, lin_event_b, Abuf, ega, idm, evt, tid);
    event_pass<4,32,2,true >(176, 0,   lin_event_b, Abuf, egb, trm, evt, tid);
    event_pass<4,32,1,true >(176, 128, lin_event_b, Abuf, egb, trm, evt, tid);
    // l=2 rows: precomputed time-part constant
    for (int idx = tid; idx < PAIRS*172; idx += NTHREADS) {
        int p = idx / 172, c = idx - p*172;
        evt[(p*3 + 2)*172 + c] += __ldg(&g_ct2[c]);
    }
    __syncthreads();

    // ---- Phase 2/3: dual gine + dual gcn2 ----
    float* GH1 = sm + R0_OFF + GH1_O;
    float* GH2 = sm + R0_OFF + GH2_O;
    GineDualGen gg{node_idx, node_embed, evt, g0};
    gemm_gine_dual(gcn_b1, Abuf, gg, GH1, GH2, tid);
    gemm_gcn2_dual(gcn_b2, GH1, GH2, feat, tid);

    // ---- Phase 4: attention ----
    float* Wq = sm + R1_OFF + WQ_O;
    gemm_direct<128,128,4,2,false,128>(g_WT_att2, att_w2_b, TgtMap{feat}, Wq, 128, tid);
    float* Wp = sm + R0_OFF + WP_O;
    gemm_direct<128,128,2,2,false,128>(g_WT_att1, att_w1_b, SrcMap{feat}, Wp, 128, tid);

    float* scb = sm + R1_OFF + SCB_O;
    {
        int pk = tid >> 3, sub = tid & 7;   // pk 0..31
        int p = pk >> 1, k = pk & 1;
        float s = 0.f;
        for (int j = sub; j < 128; j += 8)
            s += Wp[p*128 + j] * Wq[(2*p + k)*128 + j];
        s += __shfl_down_sync(0xffffffffu, s, 4, 8);
        s += __shfl_down_sync(0xffffffffu, s, 2, 8);
        s += __shfl_down_sync(0xffffffffu, s, 1, 8);
        if (sub == 0) scb[pk] = s;
    }
    __syncthreads();
    if (tid < PAIRS) {
        float s0 = scb[2*tid], s1 = scb[2*tid + 1];
        float m = fmaxf(s0, s1);
        float e0 = __expf(s0 - m), e1 = __expf(s1 - m);
        float inv = 1.f / (e0 + e1);
        scb[2*tid]     = e0 * inv;
        scb[2*tid + 1] = e1 * inv;
    }
    __syncthreads();
    float* outb = sm + R0_OFF + OUTB_O;   // overlays Wp (dead)
    for (int idx = tid; idx < PAIRS*128; idx += NTHREADS) {
        int p = idx >> 7, c = idx & 127;
        outb[idx] = feat[(p*3 + 2)*128 + c]
                  + scb[2*p]     * Wq[(2*p)*128 + c]
                  + scb[2*p + 1] * Wq[(2*p + 1)*128 + c];
    }
    __syncthreads();

    float* hb = sm + R1_OFF + HB_O;
    float* sf = sm + R1_OFF + SF_O;
    gemm_direct<64,128,2,1,true,64>(g_WT_m1, att_m1_b, PitchMap{outb,128}, hb, 64, tid);
    gemm_direct<64,64,2,1,false,64>(g_WT_m2, att_m2_b, PitchMap{hb,64}, sf, 64, tid);

    // ---- Phase 5: MLP tail (coalesced GEMMs) ----
    float* xb  = sm + R0_OFF + XB_O;      // overlays outb (dead after m1)
    float* h1b = sm + R1_OFF + H1B_O;
    float* h2b = sm + R0_OFF + H2B_O;     // overlays xb (dead after mlp1)
    for (int idx = tid; idx < PAIRS*76; idx += NTHREADS) {
        int p = idx / 76, c = idx - p*76;
        float v;
        if (c < 64) v = sf[p*64 + c];
        else        v = (__ldg(&cat_feat[g0 + p]) == (c - 64)) ? 1.f : 0.f;
        xb[idx] = v;
    }
    __syncthreads();
    gemm_direct<128,76,2,2,true,76>(g_WT_mlp1, mlp_b1, PitchMap{xb,76}, h1b, 76, tid);
    gemm_direct<64,76,2,1,true,64>(g_WT_mlp2, mlp_b2, PitchMap{h1b,76}, h2b, 64, tid);

    if (tid < PAIRS) {
        float z = __ldg(&mlp_b3[0]);
        const float* x = h2b + tid*64;
#pragma unroll 4
        for (int k = 0; k < 64; k++) z += x[k] * __ldg(&mlp_w3[k]);
        out[g0 + tid] = 1.f / (1.f + __expf(-z));
    }
}

// ---------------------------------------------------------------------------
// Launch
// ---------------------------------------------------------------------------
extern "C" void kernel_launch(void* const* d_in, const int* in_sizes, int n_in,
                              void* d_out, int out_size)
{
    const int*   node_idx      = (const int*)  d_in[0];
    const int*   edge_idx      = (const int*)  d_in[1];
    const int*   cat_feat      = (const int*)  d_in[2];
    const float* t_records     = (const float*)d_in[3];
    const float* edge_identify = (const float*)d_in[4];
    // d_in[5] = cut_time_l (unused by reference)
    const float* node_embed    = (const float*)d_in[6];
    const float* edge_embed    = (const float*)d_in[7];
    const float* basis_freq    = (const float*)d_in[8];
    const float* phase         = (const float*)d_in[9];
    const float* lin_event_w   = (const float*)d_in[10];
    const float* lin_event_b   = (const float*)d_in[11];
    const float* gcn_w1        = (const float*)d_in[12];
    const float* gcn_b1        = (const float*)d_in[13];
    const float* gcn_w2        = (const float*)d_in[14];
    const float* gcn_b2        = (const float*)d_in[15];
    const float* att_w1_w      = (const float*)d_in[16];
    const float* att_w1_b      = (const float*)d_in[17];
    const float* att_w2_w      = (const float*)d_in[18];
    const float* att_w2_b      = (const float*)d_in[19];
    const float* att_m1_w      = (const float*)d_in[20];
    const float* att_m1_b      = (const float*)d_in[21];
    const float* att_m2_w      = (const float*)d_in[22];
    const float* att_m2_b      = (const float*)d_in[23];
    const float* mlp_w1        = (const float*)d_in[24];
    const float* mlp_b1        = (const float*)d_in[25];
    const float* mlp_w2        = (const float*)d_in[26];
    const float* mlp_b2        = (const float*)d_in[27];
    const float* mlp_w3        = (const float*)d_in[28];
    const float* mlp_b3        = (const float*)d_in[29];
    float* outp = (float*)d_out;

    cudaFuncSetAttribute(fused_kernel,
                         cudaFuncAttributeMaxDynamicSharedMemorySize, SMEM_BYTES);

    prep_kernel<<<128, 256>>>(lin_event_w, gcn_w1, gcn_w2,
                              att_w1_w, att_w2_w, att_m1_w, att_m2_w,
                              mlp_w1, mlp_w2, phase);

    fused_kernel<<<NBLK, NTHREADS, SMEM_BYTES>>>(
        node_idx, edge_idx, cat_feat, t_records, edge_identify,
        node_embed, edge_embed, basis_freq, phase,
        lin_event_b, gcn_b1, gcn_b2,
        att_w1_b, att_w2_b, att_m1_b, att_m2_b,
        mlp_b1, mlp_b2, mlp_w3, mlp_b3,
        outp);
}

// round 14
// speedup vs baseline: 1.0783x; 1.0783x over previous
#include <cuda_runtime.h>
#include <math.h>
#include <stdint.h>

#define NTHREADS 256
#define PAIRS    16
#define ROWS     48
#define NBLK     2048

typedef unsigned long long ull;

// fused-kernel smem layout (floats): 18816 floats -> 3 blocks/SM
#define EVT_OFF   0
#define FEAT_OFF  8448
#define ABUF_OFF  14592
#define SMEM_FLOATS 18816
#define SMEM_BYTES (SMEM_FLOATS*4)
#define GH1_OFF   (EVT_OFF + 0)
#define GH2_OFF   (EVT_OFF + 3072)
#define WQ_OFF    (EVT_OFF + 4096)
#define WP_OFF    (EVT_OFF + 0)
#define OUTB_OFF  (ABUF_OFF + 0)
#define SC_OFF    (ABUF_OFF + 2048)
#define HB_OFF    (FEAT_OFF + 0)
#define SF_OFF    (FEAT_OFF + 1024)
#define XB_OFF    (FEAT_OFF + 2048)
#define H1_OFF    (FEAT_OFF + 3264)
#define H2_OFF    (FEAT_OFF + 4480)

__device__ __forceinline__ ull pack2(float lo, float hi) {
    ull r; asm("mov.b64 %0, {%1, %2};" : "=l"(r) : "f"(lo), "f"(hi)); return r;
}
__device__ __forceinline__ void unpack2(ull v, float& lo, float& hi) {
    asm("mov.b64 {%0, %1}, %2;" : "=f"(lo), "=f"(hi) : "l"(v));
}
__device__ __forceinline__ void fma2(ull& d, ull a, ull b) {
    asm("fma.rn.f32x2 %0, %1, %2, %0;" : "+l"(d) : "l"(a), "l"(b));
}
__device__ __forceinline__ float fsel4(float4 v, int kk) {
    return (kk==0)?v.x:(kk==1)?v.y:(kk==2)?v.z:v.w;
}

// ---------------------------------------------------------------------------
// Pre-transposed / padded weights ([k][o] layout, zero padded)
// ---------------------------------------------------------------------------
__device__ __align__(16) float g_WT_event[352*192];
__device__ __align__(16) float g_WT_gcn1 [176*64];
__device__ __align__(16) float g_WT_gcn2 [ 64*64];
__device__ __align__(16) float g_WT_att1 [128*128];
__device__ __align__(16) float g_WT_att2 [128*128];
__device__ __align__(16) float g_WT_m1   [128*64];
__device__ __align__(16) float g_WT_m2   [ 64*64];
__device__ __align__(16) float g_WT_mlp1 [76*128];
__device__ __align__(16) float g_WT_mlp2 [76*64];
__device__ __align__(16) float g_ct2     [192];

__global__ void prep_kernel(const float* __restrict__ ew,
                            const float* __restrict__ g1,
                            const float* __restrict__ g2,
                            const float* __restrict__ a1,
                            const float* __restrict__ a2,
                            const float* __restrict__ m1,
                            const float* __restrict__ m2,
                            const float* __restrict__ w1,
                            const float* __restrict__ w2,
                            const float* __restrict__ ph)
{
    int t0 = blockIdx.x*blockDim.x + threadIdx.x;
    int stride = gridDim.x*blockDim.x;
    for (int i = t0; i < 352*192; i += stride) {
        int k = i/192, o = i%192;
        g_WT_event[i] = (k < 347 && o < 172) ? ew[o*347 + k] : 0.f;
    }
    for (int i = t0; i < 176*64; i += stride) {
        int k = i/64, o = i%64;
        g_WT_gcn1[i] = (k < 172) ? g1[o*172 + k] : 0.f;
    }
    for (int i = t0; i < 64*64; i += stride) {
        int k = i/64, o = i%64;
        g_WT_gcn2[i] = g2[o*64 + k];
        g_WT_m2[i]   = m2[o*64 + k];
    }
    for (int i = t0; i < 128*128; i += stride) {
        int k = i/128, o = i%128;
        g_WT_att1[i] = a1[o*128 + k];
        g_WT_att2[i] = a2[o*128 + k];
    }
    for (int i = t0; i < 128*64; i += stride) {
        int k = i/64, o = i%64;
        g_WT_m1[i] = m1[o*128 + k];
    }
    for (int i = t0; i < 76*128; i += stride) {
        int k = i/128, o = i%128;
        g_WT_mlp1[i] = (o < 76) ? w1[o*76 + k] : 0.f;
    }
    for (int i = t0; i < 76*64; i += stride) {
        int k = i/64, o = i%64;
        g_WT_mlp2[i] = w2[o*76 + k];
    }
    for (int o = t0; o < 192; o += stride) {
        float s = 0.f;
        if (o < 172) {
            for (int d = 1; d < 172; d++)
                s += cosf(ph[d]) * ew[o*347 + 175 + d];
        }
        g_ct2[o] = s;
    }
}

// ---------------------------------------------------------------------------
// Row-pointer maps for GEMM A operands
// ---------------------------------------------------------------------------
struct PitchMap {
    const float* base; int sa;
    __device__ __forceinline__ const float* operator()(int r) const { return base + r*sa; }
};
struct TgtMap {   // attention K/V rows: r -> feat row (r>>1)*3 + (r&1)
    const float* feat;
    __device__ __forceinline__ const float* operator()(int r) const {
        return feat + ((r >> 1)*3 + (r & 1))*128;
    }
};
struct SrcMap {   // attention Q rows: p -> feat row 3p+2
    const float* feat;
    __device__ __forceinline__ const float* operator()(int r) const {
        return feat + (r*3 + 2)*128;
    }
};

// ---------------------------------------------------------------------------
// Direct GEMM (R10 core, A via row-map). 8 warps; thread (ty,tx):
// rows [ty*RT,..+RT), cols {g*64+2tx,+1}, g<P. Weights batched 4 k's.
// ---------------------------------------------------------------------------
template<int NS, int K, int RT, int P, bool RELU, int NREAL, typename AMap>
__device__ __forceinline__ void gemm_direct(
    const float* __restrict__ Wg, const float* __restrict__ bias,
    const AMap& amap,
    float* __restrict__ C, int sc, int tid)
{
    const int ty = tid >> 5, tx = tid & 31;
    ull acc[RT][P];
#pragma unroll
    for (int i = 0; i < RT; i++)
#pragma unroll
        for (int g = 0; g < P; g++) acc[i][g] = 0ull;
    const float* wq = Wg + 2*tx;
    const float* ar[RT];
#pragma unroll
    for (int i = 0; i < RT; i++) ar[i] = amap(ty*RT + i);
#pragma unroll 1
    for (int k4 = 0; k4 < K; k4 += 4) {
        ull w[4][P];
#pragma unroll
        for (int kk = 0; kk < 4; kk++)
#pragma unroll
            for (int g = 0; g < P; g++)
                w[kk][g] = __ldg(reinterpret_cast<const ull*>(wq + (k4+kk)*NS + g*64));
        float4 av[RT];
#pragma unroll
        for (int i = 0; i < RT; i++)
            av[i] = *reinterpret_cast<const float4*>(ar[i] + k4);
#pragma unroll
        for (int kk = 0; kk < 4; kk++)
#pragma unroll
            for (int i = 0; i < RT; i++) {
                float a = fsel4(av[i], kk);
                ull ad = pack2(a, a);
#pragma unroll
                for (int g = 0; g < P; g++) fma2(acc[i][g], ad, w[kk][g]);
            }
    }
#pragma unroll
    for (int i = 0; i < RT; i++)
#pragma unroll
        for (int g = 0; g < P; g++) {
            int col = g*64 + 2*tx;
            float x, y; unpack2(acc[i][g], x, y);
            int row = ty*RT + i;
            if (col < NREAL) {
                float v = x + __ldg(&bias[col]);
                if (RELU) v = fmaxf(v, 0.f);
                C[row*sc + col] = v;
            }
            if (col + 1 < NREAL) {
                float v = y + __ldg(&bias[col+1]);
                if (RELU) v = fmaxf(v, 0.f);
                C[row*sc + col + 1] = v;
            }
        }
    __syncthreads();
}

// ---------------------------------------------------------------------------
// Event generators (R10)
// ---------------------------------------------------------------------------
struct EventGenA {          // cols [0,176), 48 rows
    const int*   edge_idx;
    const float* edge_embed;
    const float* edge_identify;
    const float* t_records;
    const float* basis_freq;
    const float* phase;
    int g0;
    __device__ __forceinline__ void operator()(float* Abuf, int kc, int tid) const {
        for (int idx = tid; idx < ROWS*44; idx += NTHREADS) {
            int r = idx / 44, cc = idx - r*44;
            int c = kc + cc;
            int p = r / 3, l = r - p*3;
            int g = g0 + p;
            float v = 0.f;
            if (c < 172) {
                int e = __ldg(&edge_idx[g*3 + l]);
                v = __ldg(&edge_embed[(long)e*172 + c]);
            } else if (c < 175) {
                v = __ldg(&edge_identify[(g*3 + l)*3 + (c - 172)]);
            } else if (c == 175) {
                float dt = __ldg(&t_records[g*3 + 2]) - __ldg(&t_records[g*3 + l]);
                v = __cosf(dt * __ldg(&basis_freq[0]) + __ldg(&phase[0]));
            }
            Abuf[idx] = v;
        }
    }
};
struct EventGenB {          // cols 176+kc.., 32 rows (l != 2)
    const float* t_records;
    const float* basis_freq;
    const float* phase;
    int g0;
    __device__ __forceinline__ void operator()(float* Abuf, int kc, int tid) const {
        for (int idx = tid; idx < 32*44; idx += NTHREADS) {
            int rr = idx / 44, cc = idx - rr*44;
            int c = 176 + kc + cc;
            int p = rr >> 1, l = rr & 1;
            int g = g0 + p;
            float v = 0.f;
            if (c < 347) {
                int d = c - 175;
                float dt = __ldg(&t_records[g*3 + 2]) - __ldg(&t_records[g*3 + l]);
                v = __cosf(dt * __ldg(&basis_freq[d]) + __ldg(&phase[d]));
            }
            Abuf[idx] = v;
        }
    }
};

// Phase 1a GEMM: K=176 (4 chunks of 44), RT=6, P=3, writes evt (+bias).
__device__ __forceinline__ void gemm_event_a(
    const float* __restrict__ bias,
    float* __restrict__ Abuf, const EventGenA& gen,
    float* __restrict__ C, int tid)
{
    const int ty = tid >> 5, tx = tid & 31;
    ull acc[6][3];
#pragma unroll
    for (int i = 0; i < 6; i++)
#pragma unroll
        for (int g = 0; g < 3; g++) acc[i][g] = 0ull;

    gen(Abuf, 0, tid);
    __syncthreads();
#pragma unroll 1
    for (int kc = 0; kc < 176; kc += 44) {
        int buf = (kc / 44) & 1;
        const float* cur = Abuf + buf*2112;
        if (kc + 44 < 176) gen(Abuf + (buf^1)*2112, kc + 44, tid);
        const float* wq   = g_WT_event + kc*192 + 2*tx;
        const float* arow = cur + ty*6*44;
#pragma unroll 1
        for (int k4 = 0; k4 < 44; k4 += 4) {
            float4 av[6];
#pragma unroll
            for (int i = 0; i < 6; i++)
                av[i] = *reinterpret_cast<const float4*>(arow + i*44 + k4);
#pragma unroll
            for (int kk = 0; kk < 4; kk++) {
                ull w[3];
#pragma unroll
                for (int g = 0; g < 3; g++)
                    w[g] = __ldg(reinterpret_cast<const ull*>(wq + (k4+kk)*192 + g*64));
#pragma unroll
                for (int i = 0; i < 6; i++) {
                    float a = fsel4(av[i], kk);
                    ull ad = pack2(a, a);
#pragma unroll
                    for (int g = 0; g < 3; g++) fma2(acc[i][g], ad, w[g]);
                }
            }
        }
        __syncthreads();
    }
#pragma unroll
    for (int i = 0; i < 6; i++)
#pragma unroll
        for (int g = 0; g < 3; g++) {
            int col = g*64 + 2*tx;
            float x, y; unpack2(acc[i][g], x, y);
            int row = ty*6 + i;
            if (col < 172)     C[row*176 + col]     = x + __ldg(&bias[col]);
            if (col + 1 < 172) C[row*176 + col + 1] = y + __ldg(&bias[col+1]);
        }
    __syncthreads();
}

// Phase 1b GEMM: weight rows 176.., RT=4 over 32 rows, accumulates into evt.
__device__ __forceinline__ void gemm_event_b(
    float* __restrict__ Abuf, const EventGenB& gen,
    float* __restrict__ C, int tid)
{
    const int ty = tid >> 5, tx = tid & 31;
    ull acc[4][3];
#pragma unroll
    for (int i = 0; i < 4; i++)
#pragma unroll
        for (int g = 0; g < 3; g++) acc[i][g] = 0ull;

    gen(Abuf, 0, tid);
    __syncthreads();
#pragma unroll 1
    for (int kc = 0; kc < 176; kc += 44) {
        int buf = (kc / 44) & 1;
        const float* cur = Abuf + buf*2112;
        if (kc + 44 < 176) gen(Abuf + (buf^1)*2112, kc + 44, tid);
        const float* wq   = g_WT_event + (176 + kc)*192 + 2*tx;
        const float* arow = cur + ty*4*44;
#pragma unroll 1
        for (int k4 = 0; k4 < 44; k4 += 4) {
            float4 av[4];
#pragma unroll
            for (int i = 0; i < 4; i++)
                av[i] = *reinterpret_cast<const float4*>(arow + i*44 + k4);
#pragma unroll
            for (int kk = 0; kk < 4; kk++) {
                ull w[3];
#pragma unroll
                for (int g = 0; g < 3; g++)
                    w[g] = __ldg(reinterpret_cast<const ull*>(wq + (k4+kk)*192 + g*64));
#pragma unroll
                for (int i = 0; i < 4; i++) {
                    float a = fsel4(av[i], kk);
                    ull ad = pack2(a, a);
#pragma unroll
                    for (int g = 0; g < 3; g++) fma2(acc[i][g], ad, w[g]);
                }
            }
        }
        __syncthreads();
    }
#pragma unroll
    for (int i = 0; i < 4; i++)
#pragma unroll
        for (int g = 0; g < 3; g++) {
            int col = g*64 + 2*tx;
            float x, y; unpack2(acc[i][g], x, y);
            int rr = ty*4 + i;
            int row = (rr >> 1)*3 + (rr & 1);
            if (col < 172)     C[row*176 + col]     += x;
            if (col + 1 < 172) C[row*176 + col + 1] += y;
        }
    __syncthreads();
}

// ---------------------------------------------------------------------------
// Dual gine (R10)
// ---------------------------------------------------------------------------
struct GineDualGen {
    const int*   node_idx;
    const float* node_embed;
    const float* evt;   // smem, pitch 176
    int g0;
    __device__ __forceinline__ void operator()(float* Abuf, int kc, int tid) const {
        for (int idx = tid; idx < ROWS*44; idx += NTHREADS) {
            int r = idx / 44, cc = idx - r*44;
            int c = kc + cc;
            int p = r / 3, l = r - p*3;
            int g = g0 + p;
            float v1 = 0.f, v2 = 0.f;
            if (c < 172) {
                int ns = __ldg(&node_idx[g*6 + 2*l]);
                int nt = __ldg(&node_idx[g*6 + 2*l + 1]);
                float s = __ldg(&node_embed[(long)ns*172 + c]);
                float t = __ldg(&node_embed[(long)nt*172 + c]);
                float e = evt[r*176 + c];
                v1 = s + fmaxf(t + e, 0.f);
                v2 = t + fmaxf(s + e, 0.f);
            }
            Abuf[idx]        = v1;
            Abuf[2112 + idx] = v2;
        }
    }
};

__device__ __forceinline__ void gemm_gine_dual(
    const float* __restrict__ bias,
    float* __restrict__ Abuf, const GineDualGen& gen,
    float* __restrict__ C1, float* __restrict__ C2, int tid)
{
    const int ty = tid >> 5, tx = tid & 31;
    ull acc1[6], acc2[6];
#pragma unroll
    for (int i = 0; i < 6; i++) { acc1[i] = 0ull; acc2[i] = 0ull; }
#pragma unroll 1
    for (int kc = 0; kc < 176; kc += 44) {
        __syncthreads();
        gen(Abuf, kc, tid);
        __syncthreads();
        const float* wq = g_WT_gcn1 + kc*64 + 2*tx;
        const float* a1row = Abuf + ty*6*44;
        const float* a2row = Abuf + 2112 + ty*6*44;
#pragma unroll 1
        for (int k4 = 0; k4 < 44; k4 += 4) {
            ull w[4];
#pragma unroll
            for (int kk = 0; kk < 4; kk++)
                w[kk] = __ldg(reinterpret_cast<const ull*>(wq + (k4+kk)*64));
#pragma unroll
            for (int i = 0; i < 6; i++) {
                float4 a1 = *reinterpret_cast<const float4*>(a1row + i*44 + k4);
                float4 a2 = *reinterpret_cast<const float4*>(a2row + i*44 + k4);
#pragma unroll
                for (int kk = 0; kk < 4; kk++) {
                    fma2(acc1[i], pack2(fsel4(a1,kk), fsel4(a1,kk)), w[kk]);
                    fma2(acc2[i], pack2(fsel4(a2,kk), fsel4(a2,kk)), w[kk]);
                }
            }
        }
    }
    int col = 2*tx;
    float b0 = __ldg(&bias[col]), b1 = __ldg(&bias[col+1]);
#pragma unroll
    for (int i = 0; i < 6; i++) {
        int row = ty*6 + i;
        float x, y;
        unpack2(acc1[i], x, y);
        C1[row*64 + col]     = fmaxf(x + b0, 0.f);
        C1[row*64 + col + 1] = fmaxf(y + b1, 0.f);
        unpack2(acc2[i], x, y);
        C2[row*64 + col]     = fmaxf(x + b0, 0.f);
        C2[row*64 + col + 1] = fmaxf(y + b1, 0.f);
    }
    __syncthreads();
}

__device__ __forceinline__ void gemm_gcn2_dual(
    const float* __restrict__ bias,
    const float* __restrict__ H1, const float* __restrict__ H2,
    float* __restrict__ feat, int tid)
{
    const int ty = tid >> 5, tx = tid & 31;
    ull acc1[6], acc2[6];
#pragma unroll
    for (int i = 0; i < 6; i++) { acc1[i] = 0ull; acc2[i] = 0ull; }
    const float* wq = g_WT_gcn2 + 2*tx;
#pragma unroll 1
    for (int k4 = 0; k4 < 64; k4 += 4) {
        ull w[4];
#pragma unroll
        for (int kk = 0; kk < 4; kk++)
            w[kk] = __ldg(reinterpret_cast<const ull*>(wq + (k4+kk)*64));
#pragma unroll
        for (int i = 0; i < 6; i++) {
            float4 a1 = *reinterpret_cast<const float4*>(H1 + (ty*6+i)*64 + k4);
            float4 a2 = *reinterpret_cast<const float4*>(H2 + (ty*6+i)*64 + k4);
#pragma unroll
            for (int kk = 0; kk < 4; kk++) {
                fma2(acc1[i], pack2(fsel4(a1,kk), fsel4(a1,kk)), w[kk]);
                fma2(acc2[i], pack2(fsel4(a2,kk), fsel4(a2,kk)), w[kk]);
            }
        }
    }
    __syncthreads();
    int col = 2*tx;
    float b0 = __ldg(&bias[col]), b1 = __ldg(&bias[col+1]);
#pragma unroll
    for (int i = 0; i < 6; i++) {
        int row = ty*6 + i;
        float x, y;
        unpack2(acc1[i], x, y);
        feat[row*128 + col]      = x + b0;
        feat[row*128 + col + 1]  = y + b1;
        unpack2(acc2[i], x, y);
        feat[row*128 + 64 + col]     = x + b0;
        feat[row*128 + 64 + col + 1] = y + b1;
    }
    __syncthreads();
}

// ---------------------------------------------------------------------------
// Fused main kernel (R10 structure, row-mapped attention/tail GEMMs)
// ---------------------------------------------------------------------------
__global__ void __launch_bounds__(NTHREADS, 3)
fused_kernel(const int*   __restrict__ node_idx,
             const int*   __restrict__ edge_idx,
             const int*   __restrict__ cat_feat,
             const float* __restrict__ t_records,
             const float* __restrict__ edge_identify,
             const float* __restrict__ node_embed,
             const float* __restrict__ edge_embed,
             const float* __restrict__ basis_freq,
             const float* __restrict__ phase,
             const float* __restrict__ lin_event_b,
             const float* __restrict__ gcn_b1,
             const float* __restrict__ gcn_b2,
             const float* __restrict__ att_w1_b,
             const float* __restrict__ att_w2_b,
             const float* __restrict__ att_m1_b,
             const float* __restrict__ att_m2_b,
             const float* __restrict__ mlp_b1,
             const float* __restrict__ mlp_b2,
             const float* __restrict__ mlp_w3,
             const float* __restrict__ mlp_b3,
             float*       __restrict__ out)
{
    extern __shared__ float sm[];
    const int tid = threadIdx.x;
    const int g0  = blockIdx.x * PAIRS;

    float* evt  = sm + EVT_OFF;
    float* feat = sm + FEAT_OFF;
    float* Abuf = sm + ABUF_OFF;

    // ---- Phase 1a: event cols [0,176), all rows ----
    EventGenA ega{edge_idx, edge_embed, edge_identify, t_records, basis_freq, phase, g0};
    gemm_event_a(lin_event_b, Abuf, ega, evt, tid);

    // ---- Phase 1b: event cols [176,347), only l!=2 rows ----
    EventGenB egb{t_records, basis_freq, phase, g0};
    gemm_event_b(Abuf, egb, evt, tid);

    // ---- Phase 1c: l=2 rows get precomputed time-part constant ----
    for (int idx = tid; idx < PAIRS*172; idx += NTHREADS) {
        int p = idx / 172, c = idx - p*172;
        evt[(p*3 + 2)*176 + c] += __ldg(&g_ct2[c]);
    }
    __syncthreads();

    // ---- Phase 2: dual gine -> GH1/GH2 ----
    GineDualGen gg{node_idx, node_embed, evt, g0};
    gemm_gine_dual(gcn_b1, Abuf, gg, sm + GH1_OFF, sm + GH2_OFF, tid);

    // ---- Phase 3: dual gcn2 -> feat ----
    gemm_gcn2_dual(gcn_b2, sm + GH1_OFF, sm + GH2_OFF, feat, tid);

    // ---- Phase 4: attention (row-mapped A, no staging copies) ----
    float* Wq = sm + WQ_OFF;
    gemm_direct<128,128,4,2,false,128>(g_WT_att2, att_w2_b, TgtMap{feat}, Wq, 128, tid);
    float* Wp = sm + WP_OFF;
    gemm_direct<128,128,2,2,false,128>(g_WT_att1, att_w1_b, SrcMap{feat}, Wp, 128, tid);

    float* scb = sm + SC_OFF;
    {
        int pk = tid >> 3, sub = tid & 7;
        int p = pk >> 1, k = pk & 1;
        float s = 0.f;
        for (int j = sub; j < 128; j += 8)
            s += Wp[p*128 + j] * Wq[(2*p + k)*128 + j];
        s += __shfl_down_sync(0xffffffffu, s, 4, 8);
        s += __shfl_down_sync(0xffffffffu, s, 2, 8);
        s += __shfl_down_sync(0xffffffffu, s, 1, 8);
        if (sub == 0) scb[pk] = s;
    }
    __syncthreads();
    if (tid < PAIRS) {
        float s0 = scb[2*tid], s1 = scb[2*tid + 1];
        float m = fmaxf(s0, s1);
        float e0 = __expf(s0 - m), e1 = __expf(s1 - m);
        float inv = 1.f / (e0 + e1);
        scb[2*tid]     = e0 * inv;
        scb[2*tid + 1] = e1 * inv;
    }
    __syncthreads();
    float* outb = sm + OUTB_OFF;
    for (int idx = tid; idx < PAIRS*128; idx += NTHREADS) {
        int p = idx >> 7, c = idx & 127;
        outb[idx] = feat[(p*3 + 2)*128 + c]
                  + scb[2*p]     * Wq[(2*p)*128 + c]
                  + scb[2*p + 1] * Wq[(2*p + 1)*128 + c];
    }
    __syncthreads();

    float* hb = sm + HB_OFF;
    float* sf = sm + SF_OFF;
    gemm_direct<64,128,2,1,true,64>(g_WT_m1, att_m1_b, PitchMap{outb,128}, hb, 64, tid);
    gemm_direct<64,64,2,1,false,64>(g_WT_m2, att_m2_b, PitchMap{hb,64}, sf, 64, tid);

    // ---- Phase 5: MLP tail as coalesced GEMMs ----
    float* xb  = sm + XB_OFF;
    float* h1b = sm + H1_OFF;
    float* h2b = sm + H2_OFF;
    for (int idx = tid; idx < PAIRS*76; idx += NTHREADS) {
        int p = idx / 76, c = idx - p*76;
        float v;
        if (c < 64) v = sf[p*64 + c];
        else        v = (__ldg(&cat_feat[g0 + p]) == (c - 64)) ? 1.f : 0.f;
        xb[idx] = v;
    }
    __syncthreads();
    gemm_direct<128,76,2,2,true,76>(g_WT_mlp1, mlp_b1, PitchMap{xb,76}, h1b, 76, tid);
    gemm_direct<64,76,2,1,true,64>(g_WT_mlp2, mlp_b2, PitchMap{h1b,76}, h2b, 64, tid);

    if (tid < PAIRS) {
        float z = __ldg(&mlp_b3[0]);
        const float* x = h2b + tid*64;
#pragma unroll 4
        for (int k = 0; k < 64; k++) z += x[k] * __ldg(&mlp_w3[k]);
        out[g0 + tid] = 1.f / (1.f + __expf(-z));
    }
}

// ---------------------------------------------------------------------------
// Launch
// ---------------------------------------------------------------------------
extern "C" void kernel_launch(void* const* d_in, const int* in_sizes, int n_in,
                              void* d_out, int out_size)
{
    const int*   node_idx      = (const int*)  d_in[0];
    const int*   edge_idx      = (const int*)  d_in[1];
    const int*   cat_feat      = (const int*)  d_in[2];
    const float* t_records     = (const float*)d_in[3];
    const float* edge_identify = (const float*)d_in[4];
    // d_in[5] = cut_time_l (unused by reference)
    const float* node_embed    = (const float*)d_in[6];
    const float* edge_embed    = (const float*)d_in[7];
    const float* basis_freq    = (const float*)d_in[8];
    const float* phase         = (const float*)d_in[9];
    const float* lin_event_w   = (const float*)d_in[10];
    const float* lin_event_b   = (const float*)d_in[11];
    const float* gcn_w1        = (const float*)d_in[12];
    const float* gcn_b1        = (const float*)d_in[13];
    const float* gcn_w2        = (const float*)d_in[14];
    const float* gcn_b2        = (const float*)d_in[15];
    const float* att_w1_w      = (const float*)d_in[16];
    const float* att_w1_b      = (const float*)d_in[17];
    const float* att_w2_w      = (const float*)d_in[18];
    const float* att_w2_b      = (const float*)d_in[19];
    const float* att_m1_w      = (const float*)d_in[20];
    const float* att_m1_b      = (const float*)d_in[21];
    const float* att_m2_w      = (const float*)d_in[22];
    const float* att_m2_b      = (const float*)d_in[23];
    const float* mlp_w1        = (const float*)d_in[24];
    const float* mlp_b1        = (const float*)d_in[25];
    const float* mlp_w2        = (const float*)d_in[26];
    const float* mlp_b2        = (const float*)d_in[27];
    const float* mlp_w3        = (const float*)d_in[28];
    const float* mlp_b3        = (const float*)d_in[29];
    float* outp = (float*)d_out;

    cudaFuncSetAttribute(fused_kernel,
                         cudaFuncAttributeMaxDynamicSharedMemorySize, SMEM_BYTES);

    prep_kernel<<<128, 256>>>(lin_event_w, gcn_w1, gcn_w2,
                              att_w1_w, att_w2_w, att_m1_w, att_m2_w,
                              mlp_w1, mlp_w2, phase);

    fused_kernel<<<NBLK, NTHREADS, SMEM_BYTES>>>(
        node_idx, edge_idx, cat_feat, t_records, edge_identify,
        node_embed, edge_embed, basis_freq, phase,
        lin_event_b, gcn_b1, gcn_b2,
        att_w1_b, att_w2_b, att_m1_b, att_m2_b,
        mlp_b1, mlp_b2, mlp_w3, mlp_b3,
        outp);
}

// round 15
// speedup vs baseline: 1.1058x; 1.0255x over previous
#include <cuda_runtime.h>
#include <math.h>
#include <stdint.h>

#define NTHREADS 256
#define PAIRS    16
#define ROWS     48
#define NBLK     2048

typedef unsigned long long ull;

// fused-kernel smem layout (floats): 18816 floats -> 3 blocks/SM
#define EVT_OFF   0
#define FEAT_OFF  8448
#define ABUF_OFF  14592
#define SMEM_FLOATS 18816
#define SMEM_BYTES (SMEM_FLOATS*4)
#define GH1_OFF   (EVT_OFF + 0)
#define GH2_OFF   (EVT_OFF + 3072)
#define WQ_OFF    (EVT_OFF + 4096)
#define WP_OFF    (EVT_OFF + 0)
#define OUTB_OFF  (ABUF_OFF + 0)
#define SC_OFF    (ABUF_OFF + 2048)
#define HB_OFF    (FEAT_OFF + 0)       // 16x64
#define SF_OFF    (FEAT_OFF + 1024)    // 16x64
#define XB_OFF    (FEAT_OFF + 2048)    // 16x80 = 1280
#define H1_OFF    (FEAT_OFF + 3328)    // 16x80 = 1280
#define H2_OFF    (FEAT_OFF + 4608)    // 16x64

__device__ __forceinline__ ull pack2(float lo, float hi) {
    ull r; asm("mov.b64 %0, {%1, %2};" : "=l"(r) : "f"(lo), "f"(hi)); return r;
}
__device__ __forceinline__ void unpack2(ull v, float& lo, float& hi) {
    asm("mov.b64 {%0, %1}, %2;" : "=f"(lo), "=f"(hi) : "l"(v));
}
__device__ __forceinline__ void fma2(ull& d, ull a, ull b) {
    asm("fma.rn.f32x2 %0, %1, %2, %0;" : "+l"(d) : "l"(a), "l"(b));
}
__device__ __forceinline__ float fsel4(float4 v, int kk) {
    return (kk==0)?v.x:(kk==1)?v.y:(kk==2)?v.z:v.w;
}

// ---------------------------------------------------------------------------
// Pre-transposed / padded weights ([k][o] layout, zero padded)
// ---------------------------------------------------------------------------
__device__ __align__(16) float g_WT_event[352*192];
__device__ __align__(16) float g_WT_gcn1 [176*64];
__device__ __align__(16) float g_WT_gcn2 [ 64*64];
__device__ __align__(16) float g_WT_att1 [128*128];
__device__ __align__(16) float g_WT_att2 [128*128];
__device__ __align__(16) float g_WT_m1   [128*64];
__device__ __align__(16) float g_WT_m2   [ 64*64];
__device__ __align__(16) float g_WT_mlp1 [80*128];   // K padded 76->80 (zero rows)
__device__ __align__(16) float g_WT_mlp2 [80*64];
__device__ __align__(16) float g_ct2     [192];

__global__ void prep_kernel(const float* __restrict__ ew,
                            const float* __restrict__ g1,
                            const float* __restrict__ g2,
                            const float* __restrict__ a1,
                            const float* __restrict__ a2,
                            const float* __restrict__ m1,
                            const float* __restrict__ m2,
                            const float* __restrict__ w1,
                            const float* __restrict__ w2,
                            const float* __restrict__ ph)
{
    int t0 = blockIdx.x*blockDim.x + threadIdx.x;
    int stride = gridDim.x*blockDim.x;
    for (int i = t0; i < 352*192; i += stride) {
        int k = i/192, o = i%192;
        g_WT_event[i] = (k < 347 && o < 172) ? ew[o*347 + k] : 0.f;
    }
    for (int i = t0; i < 176*64; i += stride) {
        int k = i/64, o = i%64;
        g_WT_gcn1[i] = (k < 172) ? g1[o*172 + k] : 0.f;
    }
    for (int i = t0; i < 64*64; i += stride) {
        int k = i/64, o = i%64;
        g_WT_gcn2[i] = g2[o*64 + k];
        g_WT_m2[i]   = m2[o*64 + k];
    }
    for (int i = t0; i < 128*128; i += stride) {
        int k = i/128, o = i%128;
        g_WT_att1[i] = a1[o*128 + k];
        g_WT_att2[i] = a2[o*128 + k];
    }
    for (int i = t0; i < 128*64; i += stride) {
        int k = i/64, o = i%64;
        g_WT_m1[i] = m1[o*128 + k];
    }
    for (int i = t0; i < 80*128; i += stride) {
        int k = i/128, o = i%128;
        g_WT_mlp1[i] = (k < 76 && o < 76) ? w1[o*76 + k] : 0.f;
    }
    for (int i = t0; i < 80*64; i += stride) {
        int k = i/64, o = i%64;
        g_WT_mlp2[i] = (k < 76) ? w2[o*76 + k] : 0.f;
    }
    for (int o = t0; o < 192; o += stride) {
        float s = 0.f;
        if (o < 172) {
            for (int d = 1; d < 172; d++)
                s += cosf(ph[d]) * ew[o*347 + 175 + d];
        }
        g_ct2[o] = s;
    }
}

// ---------------------------------------------------------------------------
// Row-pointer maps for GEMM A operands
// ---------------------------------------------------------------------------
struct PitchMap {
    const float* base; int sa;
    __device__ __forceinline__ const float* operator()(int r) const { return base + r*sa; }
};
struct TgtMap {
    const float* feat;
    __device__ __forceinline__ const float* operator()(int r) const {
        return feat + ((r >> 1)*3 + (r & 1))*128;
    }
};
struct SrcMap {
    const float* feat;
    __device__ __forceinline__ const float* operator()(int r) const {
        return feat + (r*3 + 2)*128;
    }
};

// ---------------------------------------------------------------------------
// k-split GEMM: 8 warps = 2 k-groups (kg = ty>>2) x 4 row-warps (tw = ty&3).
// Each weight row is loaded by 4 warps instead of 8 (halved weight traffic).
// Two-stage epilogue: kg0 writes partial+bias; barrier; kg1 adds + ReLU.
// Cols in [NREAL, NPAD) are zeroed (padding for downstream float4 reads).
// ---------------------------------------------------------------------------
template<int NS, int K, int KH, int RT, int RH, int P, bool RELU, int NREAL,
         int NPAD, typename AMap>
__device__ __forceinline__ void gemm_ksplit(
    const float* __restrict__ Wg, const float* __restrict__ bias,
    const AMap& amap,
    float* __restrict__ C, int sc, int tid)
{
    const int ty = tid >> 5, tx = tid & 31;
    const int kg = ty >> 2, tw = ty & 3;
    const int k0 = kg ? KH : 0;
    const int k1 = kg ? K  : KH;
    ull acc[RT][P];
#pragma unroll
    for (int i = 0; i < RT; i++)
#pragma unroll
        for (int g = 0; g < P; g++) acc[i][g] = 0ull;
    const float* wq = Wg + 2*tx;
    const float* ar[RT];
#pragma unroll
    for (int i = 0; i < RT; i++) ar[i] = amap(tw*RT + i);
#pragma unroll 1
    for (int k4 = k0; k4 < k1; k4 += 4) {
        ull w[4][P];
#pragma unroll
        for (int kk = 0; kk < 4; kk++)
#pragma unroll
            for (int g = 0; g < P; g++)
                w[kk][g] = __ldg(reinterpret_cast<const ull*>(wq + (k4+kk)*NS + g*64));
#pragma unroll
        for (int r0 = 0; r0 < RT; r0 += RH) {
            float4 av[RH];
#pragma unroll
            for (int i = 0; i < RH; i++)
                av[i] = *reinterpret_cast<const float4*>(ar[r0+i] + k4);
#pragma unroll
            for (int kk = 0; kk < 4; kk++)
#pragma unroll
                for (int i = 0; i < RH; i++) {
                    float a = fsel4(av[i], kk);
                    ull ad = pack2(a, a);
#pragma unroll
                    for (int g = 0; g < P; g++) fma2(acc[r0+i][g], ad, w[kk][g]);
                }
        }
    }
    if (kg == 0) {
#pragma unroll
        for (int i = 0; i < RT; i++)
#pragma unroll
            for (int g = 0; g < P; g++) {
                int col = g*64 + 2*tx;
                float x, y; unpack2(acc[i][g], x, y);
                int row = tw*RT + i;
                if (col < NREAL)     C[row*sc + col]     = x + __ldg(&bias[col]);
                if (col + 1 < NREAL) C[row*sc + col + 1] = y + __ldg(&bias[col+1]);
            }
    }
    __syncthreads();
    if (kg == 1) {
#pragma unroll
        for (int i = 0; i < RT; i++)
#pragma unroll
            for (int g = 0; g < P; g++) {
                int col = g*64 + 2*tx;
                float x, y; unpack2(acc[i][g], x, y);
                int row = tw*RT + i;
                if (col < NREAL) {
                    float v = C[row*sc + col] + x;
                    if (RELU) v = fmaxf(v, 0.f);
                    C[row*sc + col] = v;
                } else if (col < NPAD) {
                    C[row*sc + col] = 0.f;
                }
                if (col + 1 < NREAL) {
                    float v = C[row*sc + col + 1] + y;
                    if (RELU) v = fmaxf(v, 0.f);
                    C[row*sc + col + 1] = v;
                } else if (col + 1 < NPAD) {
                    C[row*sc + col + 1] = 0.f;
                }
            }
    }
    __syncthreads();
}

// ---------------------------------------------------------------------------
// Event generators (R10)
// ---------------------------------------------------------------------------
struct EventGenA {
    const int*   edge_idx;
    const float* edge_embed;
    const float* edge_identify;
    const float* t_records;
    const float* basis_freq;
    const float* phase;
    int g0;
    __device__ __forceinline__ void operator()(float* Abuf, int kc, int tid) const {
        for (int idx = tid; idx < ROWS*44; idx += NTHREADS) {
            int r = idx / 44, cc = idx - r*44;
            int c = kc + cc;
            int p = r / 3, l = r - p*3;
            int g = g0 + p;
            float v = 0.f;
            if (c < 172) {
                int e = __ldg(&edge_idx[g*3 + l]);
                v = __ldg(&edge_embed[(long)e*172 + c]);
            } else if (c < 175) {
                v = __ldg(&edge_identify[(g*3 + l)*3 + (c - 172)]);
            } else if (c == 175) {
                float dt = __ldg(&t_records[g*3 + 2]) - __ldg(&t_records[g*3 + l]);
                v = __cosf(dt * __ldg(&basis_freq[0]) + __ldg(&phase[0]));
            }
            Abuf[idx] = v;
        }
    }
};
struct EventGenB {
    const float* t_records;
    const float* basis_freq;
    const float* phase;
    int g0;
    __device__ __forceinline__ void operator()(float* Abuf, int kc, int tid) const {
        for (int idx = tid; idx < 32*44; idx += NTHREADS) {
            int rr = idx / 44, cc = idx - rr*44;
            int c = 176 + kc + cc;
            int p = rr >> 1, l = rr & 1;
            int g = g0 + p;
            float v = 0.f;
            if (c < 347) {
                int d = c - 175;
                float dt = __ldg(&t_records[g*3 + 2]) - __ldg(&t_records[g*3 + l]);
                v = __cosf(dt * __ldg(&basis_freq[d]) + __ldg(&phase[d]));
            }
            Abuf[idx] = v;
        }
    }
};

// Phase 1a GEMM: K=176 (4 chunks of 44), RT=6, P=3, writes evt (+bias).
__device__ __forceinline__ void gemm_event_a(
    const float* __restrict__ bias,
    float* __restrict__ Abuf, const EventGenA& gen,
    float* __restrict__ C, int tid)
{
    const int ty = tid >> 5, tx = tid & 31;
    ull acc[6][3];
#pragma unroll
    for (int i = 0; i < 6; i++)
#pragma unroll
        for (int g = 0; g < 3; g++) acc[i][g] = 0ull;

    gen(Abuf, 0, tid);
    __syncthreads();
#pragma unroll 1
    for (int kc = 0; kc < 176; kc += 44) {
        int buf = (kc / 44) & 1;
        const float* cur = Abuf + buf*2112;
        if (kc + 44 < 176) gen(Abuf + (buf^1)*2112, kc + 44, tid);
        const float* wq   = g_WT_event + kc*192 + 2*tx;
        const float* arow = cur + ty*6*44;
#pragma unroll 1
        for (int k4 = 0; k4 < 44; k4 += 4) {
            float4 av[6];
#pragma unroll
            for (int i = 0; i < 6; i++)
                av[i] = *reinterpret_cast<const float4*>(arow + i*44 + k4);
#pragma unroll
            for (int kk = 0; kk < 4; kk++) {
                ull w[3];
#pragma unroll
                for (int g = 0; g < 3; g++)
                    w[g] = __ldg(reinterpret_cast<const ull*>(wq + (k4+kk)*192 + g*64));
#pragma unroll
                for (int i = 0; i < 6; i++) {
                    float a = fsel4(av[i], kk);
                    ull ad = pack2(a, a);
#pragma unroll
                    for (int g = 0; g < 3; g++) fma2(acc[i][g], ad, w[g]);
                }
            }
        }
        __syncthreads();
    }
#pragma unroll
    for (int i = 0; i < 6; i++)
#pragma unroll
        for (int g = 0; g < 3; g++) {
            int col = g*64 + 2*tx;
            float x, y; unpack2(acc[i][g], x, y);
            int row = ty*6 + i;
            if (col < 172)     C[row*176 + col]     = x + __ldg(&bias[col]);
            if (col + 1 < 172) C[row*176 + col + 1] = y + __ldg(&bias[col+1]);
        }
    __syncthreads();
}

// Phase 1b GEMM: weight rows 176.., RT=4 over 32 rows, accumulates into evt.
__device__ __forceinline__ void gemm_event_b(
    float* __restrict__ Abuf, const EventGenB& gen,
    float* __restrict__ C, int tid)
{
    const int ty = tid >> 5, tx = tid & 31;
    ull acc[4][3];
#pragma unroll
    for (int i = 0; i < 4; i++)
#pragma unroll
        for (int g = 0; g < 3; g++) acc[i][g] = 0ull;

    gen(Abuf, 0, tid);
    __syncthreads();
#pragma unroll 1
    for (int kc = 0; kc < 176; kc += 44) {
        int buf = (kc / 44) & 1;
        const float* cur = Abuf + buf*2112;
        if (kc + 44 < 176) gen(Abuf + (buf^1)*2112, kc + 44, tid);
        const float* wq   = g_WT_event + (176 + kc)*192 + 2*tx;
        const float* arow = cur + ty*4*44;
#pragma unroll 1
        for (int k4 = 0; k4 < 44; k4 += 4) {
            float4 av[4];
#pragma unroll
            for (int i = 0; i < 4; i++)
                av[i] = *reinterpret_cast<const float4*>(arow + i*44 + k4);
#pragma unroll
            for (int kk = 0; kk < 4; kk++) {
                ull w[3];
#pragma unroll
                for (int g = 0; g < 3; g++)
                    w[g] = __ldg(reinterpret_cast<const ull*>(wq + (k4+kk)*192 + g*64));
#pragma unroll
                for (int i = 0; i < 4; i++) {
                    float a = fsel4(av[i], kk);
                    ull ad = pack2(a, a);
#pragma unroll
                    for (int g = 0; g < 3; g++) fma2(acc[i][g], ad, w[g]);
                }
            }
        }
        __syncthreads();
    }
#pragma unroll
    for (int i = 0; i < 4; i++)
#pragma unroll
        for (int g = 0; g < 3; g++) {
            int col = g*64 + 2*tx;
            float x, y; unpack2(acc[i][g], x, y);
            int rr = ty*4 + i;
            int row = (rr >> 1)*3 + (rr & 1);
            if (col < 172)     C[row*176 + col]     += x;
            if (col + 1 < 172) C[row*176 + col + 1] += y;
        }
    __syncthreads();
}

// ---------------------------------------------------------------------------
// Dual gine (R10)
// ---------------------------------------------------------------------------
struct GineDualGen {
    const int*   node_idx;
    const float* node_embed;
    const float* evt;   // smem, pitch 176
    int g0;
    __device__ __forceinline__ void operator()(float* Abuf, int kc, int tid) const {
        for (int idx = tid; idx < ROWS*44; idx += NTHREADS) {
            int r = idx / 44, cc = idx - r*44;
            int c = kc + cc;
            int p = r / 3, l = r - p*3;
            int g = g0 + p;
            float v1 = 0.f, v2 = 0.f;
            if (c < 172) {
                int ns = __ldg(&node_idx[g*6 + 2*l]);
                int nt = __ldg(&node_idx[g*6 + 2*l + 1]);
                float s = __ldg(&node_embed[(long)ns*172 + c]);
                float t = __ldg(&node_embed[(long)nt*172 + c]);
                float e = evt[r*176 + c];
                v1 = s + fmaxf(t + e, 0.f);
                v2 = t + fmaxf(s + e, 0.f);
            }
            Abuf[idx]        = v1;
            Abuf[2112 + idx] = v2;
        }
    }
};

__device__ __forceinline__ void gemm_gine_dual(
    const float* __restrict__ bias,
    float* __restrict__ Abuf, const GineDualGen& gen,
    float* __restrict__ C1, float* __restrict__ C2, int tid)
{
    const int ty = tid >> 5, tx = tid & 31;
    ull acc1[6], acc2[6];
#pragma unroll
    for (int i = 0; i < 6; i++) { acc1[i] = 0ull; acc2[i] = 0ull; }
#pragma unroll 1
    for (int kc = 0; kc < 176; kc += 44) {
        __syncthreads();
        gen(Abuf, kc, tid);
        __syncthreads();
        const float* wq = g_WT_gcn1 + kc*64 + 2*tx;
        const float* a1row = Abuf + ty*6*44;
        const float* a2row = Abuf + 2112 + ty*6*44;
#pragma unroll 1
        for (int k4 = 0; k4 < 44; k4 += 4) {
            ull w[4];
#pragma unroll
            for (int kk = 0; kk < 4; kk++)
                w[kk] = __ldg(reinterpret_cast<const ull*>(wq + (k4+kk)*64));
#pragma unroll
            for (int i = 0; i < 6; i++) {
                float4 a1 = *reinterpret_cast<const float4*>(a1row + i*44 + k4);
                float4 a2 = *reinterpret_cast<const float4*>(a2row + i*44 + k4);
#pragma unroll
                for (int kk = 0; kk < 4; kk++) {
                    fma2(acc1[i], pack2(fsel4(a1,kk), fsel4(a1,kk)), w[kk]);
                    fma2(acc2[i], pack2(fsel4(a2,kk), fsel4(a2,kk)), w[kk]);
                }
            }
        }
    }
    int col = 2*tx;
    float b0 = __ldg(&bias[col]), b1 = __ldg(&bias[col+1]);
#pragma unroll
    for (int i = 0; i < 6; i++) {
        int row = ty*6 + i;
        float x, y;
        unpack2(acc1[i], x, y);
        C1[row*64 + col]     = fmaxf(x + b0, 0.f);
        C1[row*64 + col + 1] = fmaxf(y + b1, 0.f);
        unpack2(acc2[i], x, y);
        C2[row*64 + col]     = fmaxf(x + b0, 0.f);
        C2[row*64 + col + 1] = fmaxf(y + b1, 0.f);
    }
    __syncthreads();
}

__device__ __forceinline__ void gemm_gcn2_dual(
    const float* __restrict__ bias,
    const float* __restrict__ H1, const float* __restrict__ H2,
    float* __restrict__ feat, int tid)
{
    const int ty = tid >> 5, tx = tid & 31;
    ull acc1[6], acc2[6];
#pragma unroll
    for (int i = 0; i < 6; i++) { acc1[i] = 0ull; acc2[i] = 0ull; }
    const float* wq = g_WT_gcn2 + 2*tx;
#pragma unroll 1
    for (int k4 = 0; k4 < 64; k4 += 4) {
        ull w[4];
#pragma unroll
        for (int kk = 0; kk < 4; kk++)
            w[kk] = __ldg(reinterpret_cast<const ull*>(wq + (k4+kk)*64));
#pragma unroll
        for (int i = 0; i < 6; i++) {
            float4 a1 = *reinterpret_cast<const float4*>(H1 + (ty*6+i)*64 + k4);
            float4 a2 = *reinterpret_cast<const float4*>(H2 + (ty*6+i)*64 + k4);
#pragma unroll
            for (int kk = 0; kk < 4; kk++) {
                fma2(acc1[i], pack2(fsel4(a1,kk), fsel4(a1,kk)), w[kk]);
                fma2(acc2[i], pack2(fsel4(a2,kk), fsel4(a2,kk)), w[kk]);
            }
        }
    }
    __syncthreads();
    int col = 2*tx;
    float b0 = __ldg(&bias[col]), b1 = __ldg(&bias[col+1]);
#pragma unroll
    for (int i = 0; i < 6; i++) {
        int row = ty*6 + i;
        float x, y;
        unpack2(acc1[i], x, y);
        feat[row*128 + col]      = x + b0;
        feat[row*128 + col + 1]  = y + b1;
        unpack2(acc2[i], x, y);
        feat[row*128 + 64 + col]     = x + b0;
        feat[row*128 + 64 + col + 1] = y + b1;
    }
    __syncthreads();
}

// ---------------------------------------------------------------------------
// Fused main kernel
// ---------------------------------------------------------------------------
__global__ void __launch_bounds__(NTHREADS, 3)
fused_kernel(const int*   __restrict__ node_idx,
             const int*   __restrict__ edge_idx,
             const int*   __restrict__ cat_feat,
             const float* __restrict__ t_records,
             const float* __restrict__ edge_identify,
             const float* __restrict__ node_embed,
             const float* __restrict__ edge_embed,
             const float* __restrict__ basis_freq,
             const float* __restrict__ phase,
             const float* __restrict__ lin_event_b,
             const float* __restrict__ gcn_b1,
             const float* __restrict__ gcn_b2,
             const float* __restrict__ att_w1_b,
             const float* __restrict__ att_w2_b,
             const float* __restrict__ att_m1_b,
             const float* __restrict__ att_m2_b,
             const float* __restrict__ mlp_b1,
             const float* __restrict__ mlp_b2,
             const float* __restrict__ mlp_w3,
             const float* __restrict__ mlp_b3,
             float*       __restrict__ out)
{
    extern __shared__ float sm[];
    const int tid = threadIdx.x;
    const int g0  = blockIdx.x * PAIRS;

    float* evt  = sm + EVT_OFF;
    float* feat = sm + FEAT_OFF;
    float* Abuf = sm + ABUF_OFF;

    // ---- Phase 1a/1b/1c: event linear ----
    EventGenA ega{edge_idx, edge_embed, edge_identify, t_records, basis_freq, phase, g0};
    gemm_event_a(lin_event_b, Abuf, ega, evt, tid);
    EventGenB egb{t_records, basis_freq, phase, g0};
    gemm_event_b(Abuf, egb, evt, tid);
    for (int idx = tid; idx < PAIRS*172; idx += NTHREADS) {
        int p = idx / 172, c = idx - p*172;
        evt[(p*3 + 2)*176 + c] += __ldg(&g_ct2[c]);
    }
    __syncthreads();

    // ---- Phase 2/3: dual gine + dual gcn2 ----
    GineDualGen gg{node_idx, node_embed, evt, g0};
    gemm_gine_dual(gcn_b1, Abuf, gg, sm + GH1_OFF, sm + GH2_OFF, tid);
    gemm_gcn2_dual(gcn_b2, sm + GH1_OFF, sm + GH2_OFF, feat, tid);

    // ---- Phase 4: attention (k-split GEMMs) ----
    float* Wq = sm + WQ_OFF;
    gemm_ksplit<128,128,64,8,4,2,false,128,128>(g_WT_att2, att_w2_b,
                                                TgtMap{feat}, Wq, 128, tid);
    float* Wp = sm + WP_OFF;
    gemm_ksplit<128,128,64,4,4,2,false,128,128>(g_WT_att1, att_w1_b,
                                                SrcMap{feat}, Wp, 128, tid);

    float* scb = sm + SC_OFF;
    {
        int pk = tid >> 3, sub = tid & 7;
        int p = pk >> 1, k = pk & 1;
        float s = 0.f;
        for (int j = sub; j < 128; j += 8)
            s += Wp[p*128 + j] * Wq[(2*p + k)*128 + j];
        s += __shfl_down_sync(0xffffffffu, s, 4, 8);
        s += __shfl_down_sync(0xffffffffu, s, 2, 8);
        s += __shfl_down_sync(0xffffffffu, s, 1, 8);
        if (sub == 0) scb[pk] = s;
    }
    __syncthreads();
    if (tid < PAIRS) {
        float s0 = scb[2*tid], s1 = scb[2*tid + 1];
        float m = fmaxf(s0, s1);
        float e0 = __expf(s0 - m), e1 = __expf(s1 - m);
        float inv = 1.f / (e0 + e1);
        scb[2*tid]     = e0 * inv;
        scb[2*tid + 1] = e1 * inv;
    }
    __syncthreads();
    float* outb = sm + OUTB_OFF;
    for (int idx = tid; idx < PAIRS*128; idx += NTHREADS) {
        int p = idx >> 7, c = idx & 127;
        outb[idx] = feat[(p*3 + 2)*128 + c]
                  + scb[2*p]     * Wq[(2*p)*128 + c]
                  + scb[2*p + 1] * Wq[(2*p + 1)*128 + c];
    }
    __syncthreads();

    float* hb = sm + HB_OFF;
    float* sf = sm + SF_OFF;
    gemm_ksplit<64,128,64,4,4,1,true,64,64>(g_WT_m1, att_m1_b,
                                            PitchMap{outb,128}, hb, 64, tid);
    gemm_ksplit<64,64,32,4,4,1,false,64,64>(g_WT_m2, att_m2_b,
                                            PitchMap{hb,64}, sf, 64, tid);

    // ---- Phase 5: MLP tail (k-split GEMMs, K padded to 80) ----
    float* xb  = sm + XB_OFF;      // 16x80
    float* h1b = sm + H1_OFF;      // 16x80
    float* h2b = sm + H2_OFF;      // 16x64
    for (int idx = tid; idx < PAIRS*80; idx += NTHREADS) {
        int p = idx / 80, c = idx - p*80;
        float v = 0.f;
        if (c < 64)      v = sf[p*64 + c];
        else if (c < 76) v = (__ldg(&cat_feat[g0 + p]) == (c - 64)) ? 1.f : 0.f;
        xb[idx] = v;
    }
    __syncthreads();
    gemm_ksplit<128,80,40,4,4,2,true,76,80>(g_WT_mlp1, mlp_b1,
                                            PitchMap{xb,80}, h1b, 80, tid);
    gemm_ksplit<64,80,40,4,4,1,true,64,64>(g_WT_mlp2, mlp_b2,
                                           PitchMap{h1b,80}, h2b, 64, tid);

    if (tid < PAIRS) {
        float z = __ldg(&mlp_b3[0]);
        const float* x = h2b + tid*64;
#pragma unroll 4
        for (int k = 0; k < 64; k++) z += x[k] * __ldg(&mlp_w3[k]);
        out[g0 + tid] = 1.f / (1.f + __expf(-z));
    }
}

// ---------------------------------------------------------------------------
// Launch
// ---------------------------------------------------------------------------
extern "C" void kernel_launch(void* const* d_in, const int* in_sizes, int n_in,
                              void* d_out, int out_size)
{
    const int*   node_idx      = (const int*)  d_in[0];
    const int*   edge_idx      = (const int*)  d_in[1];
    const int*   cat_feat      = (const int*)  d_in[2];
    const float* t_records     = (const float*)d_in[3];
    const float* edge_identify = (const float*)d_in[4];
    // d_in[5] = cut_time_l (unused by reference)
    const float* node_embed    = (const float*)d_in[6];
    const float* edge_embed    = (const float*)d_in[7];
    const float* basis_freq    = (const float*)d_in[8];
    const float* phase         = (const float*)d_in[9];
    const float* lin_event_w   = (const float*)d_in[10];
    const float* lin_event_b   = (const float*)d_in[11];
    const float* gcn_w1        = (const float*)d_in[12];
    const float* gcn_b1        = (const float*)d_in[13];
    const float* gcn_w2        = (const float*)d_in[14];
    const float* gcn_b2        = (const float*)d_in[15];
    const float* att_w1_w      = (const float*)d_in[16];
    const float* att_w1_b      = (const float*)d_in[17];
    const float* att_w2_w      = (const float*)d_in[18];
    const float* att_w2_b      = (const float*)d_in[19];
    const float* att_m1_w      = (const float*)d_in[20];
    const float* att_m1_b      = (const float*)d_in[21];
    const float* att_m2_w      = (const float*)d_in[22];
    const float* att_m2_b      = (const float*)d_in[23];
    const float* mlp_w1        = (const float*)d_in[24];
    const float* mlp_b1        = (const float*)d_in[25];
    const float* mlp_w2        = (const float*)d_in[26];
    const float* mlp_b2        = (const float*)d_in[27];
    const float* mlp_w3        = (const float*)d_in[28];
    const float* mlp_b3        = (const float*)d_in[29];
    float* outp = (float*)d_out;

    cudaFuncSetAttribute(fused_kernel,
                         cudaFuncAttributeMaxDynamicSharedMemorySize, SMEM_BYTES);

    prep_kernel<<<128, 256>>>(lin_event_w, gcn_w1, gcn_w2,
                              att_w1_w, att_w2_w, att_m1_w, att_m2_w,
                              mlp_w1, mlp_w2, phase);

    fused_kernel<<<NBLK, NTHREADS, SMEM_BYTES>>>(
        node_idx, edge_idx, cat_feat, t_records, edge_identify,
        node_embed, edge_embed, basis_freq, phase,
        lin_event_b, gcn_b1, gcn_b2,
        att_w1_b, att_w2_b, att_m1_b, att_m2_b,
        mlp_b1, mlp_b2, mlp_w3, mlp_b3,
        outp);
}

// round 16
// speedup vs baseline: 1.1295x; 1.0215x over previous
#include <cuda_runtime.h>
#include <math.h>
#include <stdint.h>

#define NTHREADS 256
#define PAIRS    16
#define ROWS     48
#define NBLK     2048

typedef unsigned long long ull;

// fused-kernel smem layout (floats): 19008 floats = 76032 B -> 3 blocks/SM
#define EVT_OFF   0
#define FEAT_OFF  8448
#define ABUF_OFF  14592
#define SG_OFF    18816       // staged indices/dt: 192 slots
#define SMEM_FLOATS 19008
#define SMEM_BYTES (SMEM_FLOATS*4)
#define GH1_OFF   (EVT_OFF + 0)
#define GH2_OFF   (EVT_OFF + 3072)
#define WQ_OFF    (EVT_OFF + 4096)
#define WP_OFF    (EVT_OFF + 0)
#define OUTB_OFF  (ABUF_OFF + 0)
#define SC_OFF    (ABUF_OFF + 2048)
#define HB_OFF    (FEAT_OFF + 0)
#define SF_OFF    (FEAT_OFF + 1024)
#define XB_OFF    (FEAT_OFF + 2048)    // 16x80
#define H1_OFF    (FEAT_OFF + 3328)    // 16x80
#define H2_OFF    (FEAT_OFF + 4608)    // 16x64

__device__ __forceinline__ ull pack2(float lo, float hi) {
    ull r; asm("mov.b64 %0, {%1, %2};" : "=l"(r) : "f"(lo), "f"(hi)); return r;
}
__device__ __forceinline__ void unpack2(ull v, float& lo, float& hi) {
    asm("mov.b64 {%0, %1}, %2;" : "=f"(lo), "=f"(hi) : "l"(v));
}
__device__ __forceinline__ void fma2(ull& d, ull a, ull b) {
    asm("fma.rn.f32x2 %0, %1, %2, %0;" : "+l"(d) : "l"(a), "l"(b));
}
__device__ __forceinline__ float fsel4(float4 v, int kk) {
    return (kk==0)?v.x:(kk==1)?v.y:(kk==2)?v.z:v.w;
}

// ---------------------------------------------------------------------------
// Pre-transposed / padded weights ([k][o] layout, zero padded)
// ---------------------------------------------------------------------------
__device__ __align__(16) float g_WT_event[352*192];
__device__ __align__(16) float g_WT_gcn1 [176*64];
__device__ __align__(16) float g_WT_gcn2 [ 64*64];
__device__ __align__(16) float g_WT_att1 [128*128];
__device__ __align__(16) float g_WT_att2 [128*128];
__device__ __align__(16) float g_WT_m1   [128*64];
__device__ __align__(16) float g_WT_m2   [ 64*64];
__device__ __align__(16) float g_WT_mlp1 [80*128];
__device__ __align__(16) float g_WT_mlp2 [80*64];
__device__ __align__(16) float g_ct2     [192];

__global__ void prep_kernel(const float* __restrict__ ew,
                            const float* __restrict__ g1,
                            const float* __restrict__ g2,
                            const float* __restrict__ a1,
                            const float* __restrict__ a2,
                            const float* __restrict__ m1,
                            const float* __restrict__ m2,
                            const float* __restrict__ w1,
                            const float* __restrict__ w2,
                            const float* __restrict__ ph)
{
    int t0 = blockIdx.x*blockDim.x + threadIdx.x;
    int stride = gridDim.x*blockDim.x;
    for (int i = t0; i < 352*192; i += stride) {
        int k = i/192, o = i%192;
        g_WT_event[i] = (k < 347 && o < 172) ? ew[o*347 + k] : 0.f;
    }
    for (int i = t0; i < 176*64; i += stride) {
        int k = i/64, o = i%64;
        g_WT_gcn1[i] = (k < 172) ? g1[o*172 + k] : 0.f;
    }
    for (int i = t0; i < 64*64; i += stride) {
        int k = i/64, o = i%64;
        g_WT_gcn2[i] = g2[o*64 + k];
        g_WT_m2[i]   = m2[o*64 + k];
    }
    for (int i = t0; i < 128*128; i += stride) {
        int k = i/128, o = i%128;
        g_WT_att1[i] = a1[o*128 + k];
        g_WT_att2[i] = a2[o*128 + k];
    }
    for (int i = t0; i < 128*64; i += stride) {
        int k = i/64, o = i%64;
        g_WT_m1[i] = m1[o*128 + k];
    }
    for (int i = t0; i < 80*128; i += stride) {
        int k = i/128, o = i%128;
        g_WT_mlp1[i] = (k < 76 && o < 76) ? w1[o*76 + k] : 0.f;
    }
    for (int i = t0; i < 80*64; i += stride) {
        int k = i/64, o = i%64;
        g_WT_mlp2[i] = (k < 76) ? w2[o*76 + k] : 0.f;
    }
    for (int o = t0; o < 192; o += stride) {
        float s = 0.f;
        if (o < 172) {
            for (int d = 1; d < 172; d++)
                s += cosf(ph[d]) * ew[o*347 + 175 + d];
        }
        g_ct2[o] = s;
    }
}

// ---------------------------------------------------------------------------
// Row-pointer maps
// ---------------------------------------------------------------------------
struct PitchMap {
    const float* base; int sa;
    __device__ __forceinline__ const float* operator()(int r) const { return base + r*sa; }
};
struct TgtMap {
    const float* feat;
    __device__ __forceinline__ const float* operator()(int r) const {
        return feat + ((r >> 1)*3 + (r & 1))*128;
    }
};
struct SrcMap {
    const float* feat;
    __device__ __forceinline__ const float* operator()(int r) const {
        return feat + (r*3 + 2)*128;
    }
};

// ---------------------------------------------------------------------------
// k-split GEMM (R15): 2 k-groups x 4 row-warps, two-stage epilogue.
// ---------------------------------------------------------------------------
template<int NS, int K, int KH, int RT, int RH, int P, bool RELU, int NREAL,
         int NPAD, typename AMap>
__device__ __forceinline__ void gemm_ksplit(
    const float* __restrict__ Wg, const float* __restrict__ bias,
    const AMap& amap,
    float* __restrict__ C, int sc, int tid)
{
    const int ty = tid >> 5, tx = tid & 31;
    const int kg = ty >> 2, tw = ty & 3;
    const int k0 = kg ? KH : 0;
    const int k1 = kg ? K  : KH;
    ull acc[RT][P];
#pragma unroll
    for (int i = 0; i < RT; i++)
#pragma unroll
        for (int g = 0; g < P; g++) acc[i][g] = 0ull;
    const float* wq = Wg + 2*tx;
    const float* ar[RT];
#pragma unroll
    for (int i = 0; i < RT; i++) ar[i] = amap(tw*RT + i);
#pragma unroll 1
    for (int k4 = k0; k4 < k1; k4 += 4) {
        ull w[4][P];
#pragma unroll
        for (int kk = 0; kk < 4; kk++)
#pragma unroll
            for (int g = 0; g < P; g++)
                w[kk][g] = __ldg(reinterpret_cast<const ull*>(wq + (k4+kk)*NS + g*64));
#pragma unroll
        for (int r0 = 0; r0 < RT; r0 += RH) {
            float4 av[RH];
#pragma unroll
            for (int i = 0; i < RH; i++)
                av[i] = *reinterpret_cast<const float4*>(ar[r0+i] + k4);
#pragma unroll
            for (int kk = 0; kk < 4; kk++)
#pragma unroll
                for (int i = 0; i < RH; i++) {
                    float a = fsel4(av[i], kk);
                    ull ad = pack2(a, a);
#pragma unroll
                    for (int g = 0; g < P; g++) fma2(acc[r0+i][g], ad, w[kk][g]);
                }
        }
    }
    if (kg == 0) {
#pragma unroll
        for (int i = 0; i < RT; i++)
#pragma unroll
            for (int g = 0; g < P; g++) {
                int col = g*64 + 2*tx;
                float x, y; unpack2(acc[i][g], x, y);
                int row = tw*RT + i;
                if (col < NREAL)     C[row*sc + col]     = x + __ldg(&bias[col]);
                if (col + 1 < NREAL) C[row*sc + col + 1] = y + __ldg(&bias[col+1]);
            }
    }
    __syncthreads();
    if (kg == 1) {
#pragma unroll
        for (int i = 0; i < RT; i++)
#pragma unroll
            for (int g = 0; g < P; g++) {
                int col = g*64 + 2*tx;
                float x, y; unpack2(acc[i][g], x, y);
                int row = tw*RT + i;
                if (col < NREAL) {
                    float v = C[row*sc + col] + x;
                    if (RELU) v = fmaxf(v, 0.f);
                    C[row*sc + col] = v;
                } else if (col < NPAD) {
                    C[row*sc + col] = 0.f;
                }
                if (col + 1 < NREAL) {
                    float v = C[row*sc + col + 1] + y;
                    if (RELU) v = fmaxf(v, 0.f);
                    C[row*sc + col + 1] = v;
                } else if (col + 1 < NPAD) {
                    C[row*sc + col + 1] = 0.f;
                }
            }
    }
    __syncthreads();
}

// ---------------------------------------------------------------------------
// Event generators using staged indices (single-level gathers)
// ---------------------------------------------------------------------------
struct EventGenA {
    const int*   sE;          // staged edge ids, per row
    const float* sDT;         // staged dt, per row
    const float* edge_embed;
    const float* edge_identify;
    const float* basis_freq;
    const float* phase;
    int g0;
    __device__ __forceinline__ void operator()(float* Abuf, int kc, int tid) const {
        for (int idx = tid; idx < ROWS*44; idx += NTHREADS) {
            int r = idx / 44, cc = idx - r*44;
            int c = kc + cc;
            float v = 0.f;
            if (c < 172) {
                v = __ldg(&edge_embed[(long)sE[r]*172 + c]);
            } else if (c < 175) {
                v = __ldg(&edge_identify[(g0*3 + r)*3 + (c - 172)]);
            } else if (c == 175) {
                v = __cosf(sDT[r] * __ldg(&basis_freq[0]) + __ldg(&phase[0]));
            }
            Abuf[idx] = v;
        }
    }
};
struct EventGenB {
    const float* sDT;
    const float* basis_freq;
    const float* phase;
    __device__ __forceinline__ void operator()(float* Abuf, int kc, int tid) const {
        for (int idx = tid; idx < 32*44; idx += NTHREADS) {
            int rr = idx / 44, cc = idx - rr*44;
            int c = 176 + kc + cc;
            float v = 0.f;
            if (c < 347) {
                int d = c - 175;
                int r = (rr >> 1)*3 + (rr & 1);
                v = __cosf(sDT[r] * __ldg(&basis_freq[d]) + __ldg(&phase[d]));
            }
            Abuf[idx] = v;
        }
    }
};

// Phase 1a GEMM: K=176 (4 chunks of 44), RT=6, P=3, writes evt (+bias).
// NOTE: no trailing barrier (next phase writes only Abuf, ordered by its own sync).
__device__ __forceinline__ void gemm_event_a(
    const float* __restrict__ bias,
    float* __restrict__ Abuf, const EventGenA& gen,
    float* __restrict__ C, int tid)
{
    const int ty = tid >> 5, tx = tid & 31;
    ull acc[6][3];
#pragma unroll
    for (int i = 0; i < 6; i++)
#pragma unroll
        for (int g = 0; g < 3; g++) acc[i][g] = 0ull;

    gen(Abuf, 0, tid);
    __syncthreads();
#pragma unroll 1
    for (int kc = 0; kc < 176; kc += 44) {
        int buf = (kc / 44) & 1;
        const float* cur = Abuf + buf*2112;
        if (kc + 44 < 176) gen(Abuf + (buf^1)*2112, kc + 44, tid);
        const float* wq   = g_WT_event + kc*192 + 2*tx;
        const float* arow = cur + ty*6*44;
#pragma unroll 1
        for (int k4 = 0; k4 < 44; k4 += 4) {
            float4 av[6];
#pragma unroll
            for (int i = 0; i < 6; i++)
                av[i] = *reinterpret_cast<const float4*>(arow + i*44 + k4);
#pragma unroll
            for (int kk = 0; kk < 4; kk++) {
                ull w[3];
#pragma unroll
                for (int g = 0; g < 3; g++)
                    w[g] = __ldg(reinterpret_cast<const ull*>(wq + (k4+kk)*192 + g*64));
#pragma unroll
                for (int i = 0; i < 6; i++) {
                    float a = fsel4(av[i], kk);
                    ull ad = pack2(a, a);
#pragma unroll
                    for (int g = 0; g < 3; g++) fma2(acc[i][g], ad, w[g]);
                }
            }
        }
        __syncthreads();
    }
#pragma unroll
    for (int i = 0; i < 6; i++)
#pragma unroll
        for (int g = 0; g < 3; g++) {
            int col = g*64 + 2*tx;
            float x, y; unpack2(acc[i][g], x, y);
            int row = ty*6 + i;
            if (col < 172)     C[row*176 + col]     = x + __ldg(&bias[col]);
            if (col + 1 < 172) C[row*176 + col + 1] = y + __ldg(&bias[col+1]);
        }
    // no trailing sync: event B's gen writes Abuf (reads drained by in-loop
    // sync above); evt writes ordered by event B's in-loop syncs.
}

// Phase 1b GEMM: weight rows 176.., RT=4 over 32 rows, accumulates into evt
// rows l!=2. No trailing barrier (phase1c touches only l==2 rows).
__device__ __forceinline__ void gemm_event_b(
    float* __restrict__ Abuf, const EventGenB& gen,
    float* __restrict__ C, int tid)
{
    const int ty = tid >> 5, tx = tid & 31;
    ull acc[4][3];
#pragma unroll
    for (int i = 0; i < 4; i++)
#pragma unroll
        for (int g = 0; g < 3; g++) acc[i][g] = 0ull;

    gen(Abuf, 0, tid);
    __syncthreads();
#pragma unroll 1
    for (int kc = 0; kc < 176; kc += 44) {
        int buf = (kc / 44) & 1;
        const float* cur = Abuf + buf*2112;
        if (kc + 44 < 176) gen(Abuf + (buf^1)*2112, kc + 44, tid);
        const float* wq   = g_WT_event + (176 + kc)*192 + 2*tx;
        const float* arow = cur + ty*4*44;
#pragma unroll 1
        for (int k4 = 0; k4 < 44; k4 += 4) {
            float4 av[4];
#pragma unroll
            for (int i = 0; i < 4; i++)
                av[i] = *reinterpret_cast<const float4*>(arow + i*44 + k4);
#pragma unroll
            for (int kk = 0; kk < 4; kk++) {
                ull w[3];
#pragma unroll
                for (int g = 0; g < 3; g++)
                    w[g] = __ldg(reinterpret_cast<const ull*>(wq + (k4+kk)*192 + g*64));
#pragma unroll
                for (int i = 0; i < 4; i++) {
                    float a = fsel4(av[i], kk);
                    ull ad = pack2(a, a);
#pragma unroll
                    for (int g = 0; g < 3; g++) fma2(acc[i][g], ad, w[g]);
                }
            }
        }
        __syncthreads();
    }
#pragma unroll
    for (int i = 0; i < 4; i++)
#pragma unroll
        for (int g = 0; g < 3; g++) {
            int col = g*64 + 2*tx;
            float x, y; unpack2(acc[i][g], x, y);
            int rr = ty*4 + i;
            int row = (rr >> 1)*3 + (rr & 1);
            if (col < 172)     C[row*176 + col]     += x;
            if (col + 1 < 172) C[row*176 + col + 1] += y;
        }
}

// ---------------------------------------------------------------------------
// Dual gine with staged node indices
// ---------------------------------------------------------------------------
struct GineDualGen {
    const int*   sNS;
    const int*   sNT;
    const float* node_embed;
    const float* evt;   // smem, pitch 176
    __device__ __forceinline__ void operator()(float* Abuf, int kc, int tid) const {
        for (int idx = tid; idx < ROWS*44; idx += NTHREADS) {
            int r = idx / 44, cc = idx - r*44;
            int c = kc + cc;
            float v1 = 0.f, v2 = 0.f;
            if (c < 172) {
                float s = __ldg(&node_embed[(long)sNS[r]*172 + c]);
                float t = __ldg(&node_embed[(long)sNT[r]*172 + c]);
                float e = evt[r*176 + c];
                v1 = s + fmaxf(t + e, 0.f);
                v2 = t + fmaxf(s + e, 0.f);
            }
            Abuf[idx]        = v1;
            Abuf[2112 + idx] = v2;
        }
    }
};

__device__ __forceinline__ void gemm_gine_dual(
    const float* __restrict__ bias,
    float* __restrict__ Abuf, const GineDualGen& gen,
    float* __restrict__ C1, float* __restrict__ C2, int tid)
{
    const int ty = tid >> 5, tx = tid & 31;
    ull acc1[6], acc2[6];
#pragma unroll
    for (int i = 0; i < 6; i++) { acc1[i] = 0ull; acc2[i] = 0ull; }
#pragma unroll 1
    for (int kc = 0; kc < 176; kc += 44) {
        __syncthreads();
        gen(Abuf, kc, tid);
        __syncthreads();
        const float* wq = g_WT_gcn1 + kc*64 + 2*tx;
        const float* a1row = Abuf + ty*6*44;
        const float* a2row = Abuf + 2112 + ty*6*44;
#pragma unroll 1
        for (int k4 = 0; k4 < 44; k4 += 4) {
            ull w[4];
#pragma unroll
            for (int kk = 0; kk < 4; kk++)
                w[kk] = __ldg(reinterpret_cast<const ull*>(wq + (k4+kk)*64));
#pragma unroll
            for (int i = 0; i < 6; i++) {
                float4 a1 = *reinterpret_cast<const float4*>(a1row + i*44 + k4);
                float4 a2 = *reinterpret_cast<const float4*>(a2row + i*44 + k4);
#pragma unroll
                for (int kk = 0; kk < 4; kk++) {
                    fma2(acc1[i], pack2(fsel4(a1,kk), fsel4(a1,kk)), w[kk]);
                    fma2(acc2[i], pack2(fsel4(a2,kk), fsel4(a2,kk)), w[kk]);
                }
            }
        }
    }
    int col = 2*tx;
    float b0 = __ldg(&bias[col]), b1 = __ldg(&bias[col+1]);
#pragma unroll
    for (int i = 0; i < 6; i++) {
        int row = ty*6 + i;
        float x, y;
        unpack2(acc1[i], x, y);
        C1[row*64 + col]     = fmaxf(x + b0, 0.f);
        C1[row*64 + col + 1] = fmaxf(y + b1, 0.f);
        unpack2(acc2[i], x, y);
        C2[row*64 + col]     = fmaxf(x + b0, 0.f);
        C2[row*64 + col + 1] = fmaxf(y + b1, 0.f);
    }
    __syncthreads();
}

__device__ __forceinline__ void gemm_gcn2_dual(
    const float* __restrict__ bias,
    const float* __restrict__ H1, const float* __restrict__ H2,
    float* __restrict__ feat, int tid)
{
    const int ty = tid >> 5, tx = tid & 31;
    ull acc1[6], acc2[6];
#pragma unroll
    for (int i = 0; i < 6; i++) { acc1[i] = 0ull; acc2[i] = 0ull; }
    const float* wq = g_WT_gcn2 + 2*tx;
#pragma unroll 1
    for (int k4 = 0; k4 < 64; k4 += 4) {
        ull w[4];
#pragma unroll
        for (int kk = 0; kk < 4; kk++)
            w[kk] = __ldg(reinterpret_cast<const ull*>(wq + (k4+kk)*64));
#pragma unroll
        for (int i = 0; i < 6; i++) {
            float4 a1 = *reinterpret_cast<const float4*>(H1 + (ty*6+i)*64 + k4);
            float4 a2 = *reinterpret_cast<const float4*>(H2 + (ty*6+i)*64 + k4);
#pragma unroll
            for (int kk = 0; kk < 4; kk++) {
                fma2(acc1[i], pack2(fsel4(a1,kk), fsel4(a1,kk)), w[kk]);
                fma2(acc2[i], pack2(fsel4(a2,kk), fsel4(a2,kk)), w[kk]);
            }
        }
    }
    __syncthreads();
    int col = 2*tx;
    float b0 = __ldg(&bias[col]), b1 = __ldg(&bias[col+1]);
#pragma unroll
    for (int i = 0; i < 6; i++) {
        int row = ty*6 + i;
        float x, y;
        unpack2(acc1[i], x, y);
        feat[row*128 + col]      = x + b0;
        feat[row*128 + col + 1]  = y + b1;
        unpack2(acc2[i], x, y);
        feat[row*128 + 64 + col]     = x + b0;
        feat[row*128 + 64 + col + 1] = y + b1;
    }
    __syncthreads();
}

// ---------------------------------------------------------------------------
// Fused main kernel
// ---------------------------------------------------------------------------
__global__ void __launch_bounds__(NTHREADS, 3)
fused_kernel(const int*   __restrict__ node_idx,
             const int*   __restrict__ edge_idx,
             const int*   __restrict__ cat_feat,
             const float* __restrict__ t_records,
             const float* __restrict__ edge_identify,
             const float* __restrict__ node_embed,
             const float* __restrict__ edge_embed,
             const float* __restrict__ basis_freq,
             const float* __restrict__ phase,
             const float* __restrict__ lin_event_b,
             const float* __restrict__ gcn_b1,
             const float* __restrict__ gcn_b2,
             const float* __restrict__ att_w1_b,
             const float* __restrict__ att_w2_b,
             const float* __restrict__ att_m1_b,
             const float* __restrict__ att_m2_b,
             const float* __restrict__ mlp_b1,
             const float* __restrict__ mlp_b2,
             const float* __restrict__ mlp_w3,
             const float* __restrict__ mlp_b3,
             float*       __restrict__ out)
{
    extern __shared__ float sm[];
    const int tid = threadIdx.x;
    const int g0  = blockIdx.x * PAIRS;

    float* evt  = sm + EVT_OFF;
    float* feat = sm + FEAT_OFF;
    float* Abuf = sm + ABUF_OFF;
    int*   sNS  = reinterpret_cast<int*>(sm + SG_OFF);
    int*   sNT  = sNS + 48;
    int*   sE   = sNS + 96;
    float* sDT  = sm + SG_OFF + 144;

    // ---- Phase 0: stage indices + dt (kills 2-level gather chains) ----
    if (tid < ROWS) {
        int p = tid / 3, l = tid - p*3;
        int g = g0 + p;
        sNS[tid] = __ldg(&node_idx[g*6 + 2*l]);
        sNT[tid] = __ldg(&node_idx[g*6 + 2*l + 1]);
        sE[tid]  = __ldg(&edge_idx[g*3 + l]);
        sDT[tid] = __ldg(&t_records[g*3 + 2]) - __ldg(&t_records[g*3 + l]);
    }
    __syncthreads();

    // ---- Phase 1a/1b/1c: event linear ----
    EventGenA ega{sE, sDT, edge_embed, edge_identify, basis_freq, phase, g0};
    gemm_event_a(lin_event_b, Abuf, ega, evt, tid);
    EventGenB egb{sDT, basis_freq, phase};
    gemm_event_b(Abuf, egb, evt, tid);
    for (int idx = tid; idx < PAIRS*172; idx += NTHREADS) {
        int p = idx / 172, c = idx - p*172;
        evt[(p*3 + 2)*176 + c] += __ldg(&g_ct2[c]);
    }
    // (no barrier: gine's in-loop leading sync orders evt before its gen reads)

    // ---- Phase 2/3: dual gine + dual gcn2 ----
    GineDualGen gg{sNS, sNT, node_embed, evt};
    gemm_gine_dual(gcn_b1, Abuf, gg, sm + GH1_OFF, sm + GH2_OFF, tid);
    gemm_gcn2_dual(gcn_b2, sm + GH1_OFF, sm + GH2_OFF, feat, tid);

    // ---- Phase 4: attention (k-split GEMMs, row-mapped A) ----
    float* Wq = sm + WQ_OFF;
    gemm_ksplit<128,128,64,8,4,2,false,128,128>(g_WT_att2, att_w2_b,
                                                TgtMap{feat}, Wq, 128, tid);
    float* Wp = sm + WP_OFF;
    gemm_ksplit<128,128,64,4,4,2,false,128,128>(g_WT_att1, att_w1_b,
                                                SrcMap{feat}, Wp, 128, tid);

    float* scb = sm + SC_OFF;
    {
        int pk = tid >> 3, sub = tid & 7;
        int p = pk >> 1, k = pk & 1;
        float s = 0.f;
        for (int j = sub; j < 128; j += 8)
            s += Wp[p*128 + j] * Wq[(2*p + k)*128 + j];
        s += __shfl_down_sync(0xffffffffu, s, 4, 8);
        s += __shfl_down_sync(0xffffffffu, s, 2, 8);
        s += __shfl_down_sync(0xffffffffu, s, 1, 8);
        if (sub == 0) scb[pk] = s;
    }
    __syncthreads();
    // softmax folded into the combine loop (no extra barrier / serial step)
    float* outb = sm + OUTB_OFF;
    for (int idx = tid; idx < PAIRS*128; idx += NTHREADS) {
        int p = idx >> 7, c = idx & 127;
        float s0 = scb[2*p], s1 = scb[2*p + 1];
        float m = fmaxf(s0, s1);
        float e0 = __expf(s0 - m), e1 = __expf(s1 - m);
        float inv = 1.f / (e0 + e1);
        outb[idx] = feat[(p*3 + 2)*128 + c]
                  + (e0*inv) * Wq[(2*p)*128 + c]
                  + (e1*inv) * Wq[(2*p + 1)*128 + c];
    }
    __syncthreads();

    float* hb = sm + HB_OFF;
    float* sf = sm + SF_OFF;
    gemm_ksplit<64,128,64,4,4,1,true,64,64>(g_WT_m1, att_m1_b,
                                            PitchMap{outb,128}, hb, 64, tid);
    gemm_ksplit<64,64,32,4,4,1,false,64,64>(g_WT_m2, att_m2_b,
                                            PitchMap{hb,64}, sf, 64, tid);

    // ---- Phase 5: MLP tail (k-split GEMMs, K padded to 80) ----
    float* xb  = sm + XB_OFF;
    float* h1b = sm + H1_OFF;
    float* h2b = sm + H2_OFF;
    for (int idx = tid; idx < PAIRS*80; idx += NTHREADS) {
        int p = idx / 80, c = idx - p*80;
        float v = 0.f;
        if (c < 64)      v = sf[p*64 + c];
        else if (c < 76) v = (__ldg(&cat_feat[g0 + p]) == (c - 64)) ? 1.f : 0.f;
        xb[idx] = v;
    }
    __syncthreads();
    gemm_ksplit<128,80,40,4,4,2,true,76,80>(g_WT_mlp1, mlp_b1,
                                            PitchMap{xb,80}, h1b, 80, tid);
    gemm_ksplit<64,80,40,4,4,1,true,64,64>(g_WT_mlp2, mlp_b2,
                                           PitchMap{h1b,80}, h2b, 64, tid);

    if (tid < PAIRS) {
        float z = __ldg(&mlp_b3[0]);
        const float* x = h2b + tid*64;
#pragma unroll 4
        for (int k = 0; k < 64; k++) z += x[k] * __ldg(&mlp_w3[k]);
        out[g0 + tid] = 1.f / (1.f + __expf(-z));
    }
}

// ---------------------------------------------------------------------------
// Launch
// ---------------------------------------------------------------------------
extern "C" void kernel_launch(void* const* d_in, const int* in_sizes, int n_in,
                              void* d_out, int out_size)
{
    const int*   node_idx      = (const int*)  d_in[0];
    const int*   edge_idx      = (const int*)  d_in[1];
    const int*   cat_feat      = (const int*)  d_in[2];
    const float* t_records     = (const float*)d_in[3];
    const float* edge_identify = (const float*)d_in[4];
    // d_in[5] = cut_time_l (unused by reference)
    const float* node_embed    = (const float*)d_in[6];
    const float* edge_embed    = (const float*)d_in[7];
    const float* basis_freq    = (const float*)d_in[8];
    const float* phase         = (const float*)d_in[9];
    const float* lin_event_w   = (const float*)d_in[10];
    const float* lin_event_b   = (const float*)d_in[11];
    const float* gcn_w1        = (const float*)d_in[12];
    const float* gcn_b1        = (const float*)d_in[13];
    const float* gcn_w2        = (const float*)d_in[14];
    const float* gcn_b2        = (const float*)d_in[15];
    const float* att_w1_w      = (const float*)d_in[16];
    const float* att_w1_b      = (const float*)d_in[17];
    const float* att_w2_w      = (const float*)d_in[18];
    const float* att_w2_b      = (const float*)d_in[19];
    const float* att_m1_w      = (const float*)d_in[20];
    const float* att_m1_b      = (const float*)d_in[21];
    const float* att_m2_w      = (const float*)d_in[22];
    const float* att_m2_b      = (const float*)d_in[23];
    const float* mlp_w1        = (const float*)d_in[24];
    const float* mlp_b1        = (const float*)d_in[25];
    const float* mlp_w2        = (const float*)d_in[26];
    const float* mlp_b2        = (const float*)d_in[27];
    const float* mlp_w3        = (const float*)d_in[28];
    const float* mlp_b3        = (const float*)d_in[29];
    float* outp = (float*)d_out;

    cudaFuncSetAttribute(fused_kernel,
                         cudaFuncAttributeMaxDynamicSharedMemorySize, SMEM_BYTES);

    prep_kernel<<<128, 256>>>(lin_event_w, gcn_w1, gcn_w2,
                              att_w1_w, att_w2_w, att_m1_w, att_m2_w,
                              mlp_w1, mlp_w2, phase);

    fused_kernel<<<NBLK, NTHREADS, SMEM_BYTES>>>(
        node_idx, edge_idx, cat_feat, t_records, edge_identify,
        node_embed, edge_embed, basis_freq, phase,
        lin_event_b, gcn_b1, gcn_b2,
        att_w1_b, att_w2_b, att_m1_b, att_m2_b,
        mlp_b1, mlp_b2, mlp_w3, mlp_b3,
        outp);
}

// round 17
// speedup vs baseline: 1.1400x; 1.0093x over previous
#include <cuda_runtime.h>
#include <math.h>
#include <stdint.h>

#define NTHREADS 256
#define PAIRS    16
#define ROWS     48
#define NBLK     2048

typedef unsigned long long ull;

// fused-kernel smem layout (floats): 19008 floats = 76032 B -> 3 blocks/SM
#define EVT_OFF   0
#define FEAT_OFF  8448
#define ABUF_OFF  14592
#define SG_OFF    18816       // staged indices/dt: 192 slots
#define SMEM_FLOATS 19008
#define SMEM_BYTES (SMEM_FLOATS*4)
#define GH1_OFF   (EVT_OFF + 0)
#define GH2_OFF   (EVT_OFF + 3072)
#define WQ_OFF    (EVT_OFF + 4096)
#define WP_OFF    (EVT_OFF + 0)
#define OUTB_OFF  (ABUF_OFF + 0)
#define SC_OFF    (ABUF_OFF + 2048)
#define HB_OFF    (FEAT_OFF + 0)
#define SF_OFF    (FEAT_OFF + 1024)
#define XB_OFF    (FEAT_OFF + 2048)    // 16x80
#define H1_OFF    (FEAT_OFF + 3328)    // 16x80
#define H2_OFF    (FEAT_OFF + 4608)    // 16x64

__device__ __forceinline__ ull pack2(float lo, float hi) {
    ull r; asm("mov.b64 %0, {%1, %2};" : "=l"(r) : "f"(lo), "f"(hi)); return r;
}
__device__ __forceinline__ void unpack2(ull v, float& lo, float& hi) {
    asm("mov.b64 {%0, %1}, %2;" : "=f"(lo), "=f"(hi) : "l"(v));
}
__device__ __forceinline__ void fma2(ull& d, ull a, ull b) {
    asm("fma.rn.f32x2 %0, %1, %2, %0;" : "+l"(d) : "l"(a), "l"(b));
}
__device__ __forceinline__ float fsel4(float4 v, int kk) {
    return (kk==0)?v.x:(kk==1)?v.y:(kk==2)?v.z:v.w;
}

// ---------------------------------------------------------------------------
// Pre-transposed / padded weights ([k][o] layout, zero padded)
// ---------------------------------------------------------------------------
__device__ __align__(16) float g_WT_event[352*192];
__device__ __align__(16) float g_WT_gcn1 [176*64];
__device__ __align__(16) float g_WT_gcn2 [ 64*64];
__device__ __align__(16) float g_WT_att1 [128*128];
__device__ __align__(16) float g_WT_att2 [128*128];
__device__ __align__(16) float g_WT_m1   [128*64];
__device__ __align__(16) float g_WT_m2   [ 64*64];
__device__ __align__(16) float g_WT_mlp1 [80*128];
__device__ __align__(16) float g_WT_mlp2 [80*64];
__device__ __align__(16) float g_ct2     [192];

__global__ void prep_kernel(const float* __restrict__ ew,
                            const float* __restrict__ g1,
                            const float* __restrict__ g2,
                            const float* __restrict__ a1,
                            const float* __restrict__ a2,
                            const float* __restrict__ m1,
                            const float* __restrict__ m2,
                            const float* __restrict__ w1,
                            const float* __restrict__ w2,
                            const float* __restrict__ ph)
{
    int t0 = blockIdx.x*blockDim.x + threadIdx.x;
    int stride = gridDim.x*blockDim.x;
    for (int i = t0; i < 352*192; i += stride) {
        int k = i/192, o = i%192;
        g_WT_event[i] = (k < 347 && o < 172) ? ew[o*347 + k] : 0.f;
    }
    for (int i = t0; i < 176*64; i += stride) {
        int k = i/64, o = i%64;
        g_WT_gcn1[i] = (k < 172) ? g1[o*172 + k] : 0.f;
    }
    for (int i = t0; i < 64*64; i += stride) {
        int k = i/64, o = i%64;
        g_WT_gcn2[i] = g2[o*64 + k];
        g_WT_m2[i]   = m2[o*64 + k];
    }
    for (int i = t0; i < 128*128; i += stride) {
        int k = i/128, o = i%128;
        g_WT_att1[i] = a1[o*128 + k];
        g_WT_att2[i] = a2[o*128 + k];
    }
    for (int i = t0; i < 128*64; i += stride) {
        int k = i/64, o = i%64;
        g_WT_m1[i] = m1[o*128 + k];
    }
    for (int i = t0; i < 80*128; i += stride) {
        int k = i/128, o = i%128;
        g_WT_mlp1[i] = (k < 76 && o < 76) ? w1[o*76 + k] : 0.f;
    }
    for (int i = t0; i < 80*64; i += stride) {
        int k = i/64, o = i%64;
        g_WT_mlp2[i] = (k < 76) ? w2[o*76 + k] : 0.f;
    }
    for (int o = t0; o < 192; o += stride) {
        float s = 0.f;
        if (o < 172) {
            for (int d = 1; d < 172; d++)
                s += cosf(ph[d]) * ew[o*347 + 175 + d];
        }
        g_ct2[o] = s;
    }
}

// ---------------------------------------------------------------------------
// Row-pointer maps
// ---------------------------------------------------------------------------
struct PitchMap {
    const float* base; int sa;
    __device__ __forceinline__ const float* operator()(int r) const { return base + r*sa; }
};
struct TgtMap {
    const float* feat;
    __device__ __forceinline__ const float* operator()(int r) const {
        return feat + ((r >> 1)*3 + (r & 1))*128;
    }
};
struct SrcMap {
    const float* feat;
    __device__ __forceinline__ const float* operator()(int r) const {
        return feat + (r*3 + 2)*128;
    }
};

// ---------------------------------------------------------------------------
// k-split GEMM (R15): 2 k-groups x 4 row-warps, two-stage epilogue.
// ---------------------------------------------------------------------------
template<int NS, int K, int KH, int RT, int RH, int P, bool RELU, int NREAL,
         int NPAD, typename AMap>
__device__ __forceinline__ void gemm_ksplit(
    const float* __restrict__ Wg, const float* __restrict__ bias,
    const AMap& amap,
    float* __restrict__ C, int sc, int tid)
{
    const int ty = tid >> 5, tx = tid & 31;
    const int kg = ty >> 2, tw = ty & 3;
    const int k0 = kg ? KH : 0;
    const int k1 = kg ? K  : KH;
    ull acc[RT][P];
#pragma unroll
    for (int i = 0; i < RT; i++)
#pragma unroll
        for (int g = 0; g < P; g++) acc[i][g] = 0ull;
    const float* wq = Wg + 2*tx;
    const float* ar[RT];
#pragma unroll
    for (int i = 0; i < RT; i++) ar[i] = amap(tw*RT + i);
#pragma unroll 1
    for (int k4 = k0; k4 < k1; k4 += 4) {
        ull w[4][P];
#pragma unroll
        for (int kk = 0; kk < 4; kk++)
#pragma unroll
            for (int g = 0; g < P; g++)
                w[kk][g] = __ldg(reinterpret_cast<const ull*>(wq + (k4+kk)*NS + g*64));
#pragma unroll
        for (int r0 = 0; r0 < RT; r0 += RH) {
            float4 av[RH];
#pragma unroll
            for (int i = 0; i < RH; i++)
                av[i] = *reinterpret_cast<const float4*>(ar[r0+i] + k4);
#pragma unroll
            for (int kk = 0; kk < 4; kk++)
#pragma unroll
                for (int i = 0; i < RH; i++) {
                    float a = fsel4(av[i], kk);
                    ull ad = pack2(a, a);
#pragma unroll
                    for (int g = 0; g < P; g++) fma2(acc[r0+i][g], ad, w[kk][g]);
                }
        }
    }
    if (kg == 0) {
#pragma unroll
        for (int i = 0; i < RT; i++)
#pragma unroll
            for (int g = 0; g < P; g++) {
                int col = g*64 + 2*tx;
                float x, y; unpack2(acc[i][g], x, y);
                int row = tw*RT + i;
                if (col < NREAL)     C[row*sc + col]     = x + __ldg(&bias[col]);
                if (col + 1 < NREAL) C[row*sc + col + 1] = y + __ldg(&bias[col+1]);
            }
    }
    __syncthreads();
    if (kg == 1) {
#pragma unroll
        for (int i = 0; i < RT; i++)
#pragma unroll
            for (int g = 0; g < P; g++) {
                int col = g*64 + 2*tx;
                float x, y; unpack2(acc[i][g], x, y);
                int row = tw*RT + i;
                if (col < NREAL) {
                    float v = C[row*sc + col] + x;
                    if (RELU) v = fmaxf(v, 0.f);
                    C[row*sc + col] = v;
                } else if (col < NPAD) {
                    C[row*sc + col] = 0.f;
                }
                if (col + 1 < NREAL) {
                    float v = C[row*sc + col + 1] + y;
                    if (RELU) v = fmaxf(v, 0.f);
                    C[row*sc + col + 1] = v;
                } else if (col + 1 < NPAD) {
                    C[row*sc + col + 1] = 0.f;
                }
            }
    }
    __syncthreads();
}

// ---------------------------------------------------------------------------
// Event generators using staged indices (single-level gathers)
// ---------------------------------------------------------------------------
struct EventGenA {
    const int*   sE;
    const float* sDT;
    const float* edge_embed;
    const float* edge_identify;
    const float* basis_freq;
    const float* phase;
    int g0;
    __device__ __forceinline__ void operator()(float* Abuf, int kc, int tid) const {
        for (int idx = tid; idx < ROWS*44; idx += NTHREADS) {
            int r = idx / 44, cc = idx - r*44;
            int c = kc + cc;
            float v = 0.f;
            if (c < 172) {
                v = __ldg(&edge_embed[(long)sE[r]*172 + c]);
            } else if (c < 175) {
                v = __ldg(&edge_identify[(g0*3 + r)*3 + (c - 172)]);
            } else if (c == 175) {
                v = __cosf(sDT[r] * __ldg(&basis_freq[0]) + __ldg(&phase[0]));
            }
            Abuf[idx] = v;
        }
    }
};
struct EventGenB {
    const float* sDT;
    const float* basis_freq;
    const float* phase;
    __device__ __forceinline__ void operator()(float* Abuf, int kc, int tid) const {
        for (int idx = tid; idx < 32*44; idx += NTHREADS) {
            int rr = idx / 44, cc = idx - rr*44;
            int c = 176 + kc + cc;
            float v = 0.f;
            if (c < 347) {
                int d = c - 175;
                int r = (rr >> 1)*3 + (rr & 1);
                v = __cosf(sDT[r] * __ldg(&basis_freq[d]) + __ldg(&phase[d]));
            }
            Abuf[idx] = v;
        }
    }
};

// Phase 1a GEMM: K=176 (4 chunks of 44), RT=6, P=3, writes evt (+bias).
__device__ __forceinline__ void gemm_event_a(
    const float* __restrict__ bias,
    float* __restrict__ Abuf, const EventGenA& gen,
    float* __restrict__ C, int tid)
{
    const int ty = tid >> 5, tx = tid & 31;
    ull acc[6][3];
#pragma unroll
    for (int i = 0; i < 6; i++)
#pragma unroll
        for (int g = 0; g < 3; g++) acc[i][g] = 0ull;

    gen(Abuf, 0, tid);
    __syncthreads();
#pragma unroll 1
    for (int kc = 0; kc < 176; kc += 44) {
        int buf = (kc / 44) & 1;
        const float* cur = Abuf + buf*2112;
        if (kc + 44 < 176) gen(Abuf + (buf^1)*2112, kc + 44, tid);
        const float* wq   = g_WT_event + kc*192 + 2*tx;
        const float* arow = cur + ty*6*44;
#pragma unroll 1
        for (int k4 = 0; k4 < 44; k4 += 4) {
            float4 av[6];
#pragma unroll
            for (int i = 0; i < 6; i++)
                av[i] = *reinterpret_cast<const float4*>(arow + i*44 + k4);
#pragma unroll
            for (int kk = 0; kk < 4; kk++) {
                ull w[3];
#pragma unroll
                for (int g = 0; g < 3; g++)
                    w[g] = __ldg(reinterpret_cast<const ull*>(wq + (k4+kk)*192 + g*64));
#pragma unroll
                for (int i = 0; i < 6; i++) {
                    float a = fsel4(av[i], kk);
                    ull ad = pack2(a, a);
#pragma unroll
                    for (int g = 0; g < 3; g++) fma2(acc[i][g], ad, w[g]);
                }
            }
        }
        __syncthreads();
    }
#pragma unroll
    for (int i = 0; i < 6; i++)
#pragma unroll
        for (int g = 0; g < 3; g++) {
            int col = g*64 + 2*tx;
            float x, y; unpack2(acc[i][g], x, y);
            int row = ty*6 + i;
            if (col < 172)     C[row*176 + col]     = x + __ldg(&bias[col]);
            if (col + 1 < 172) C[row*176 + col + 1] = y + __ldg(&bias[col+1]);
        }
}

// Phase 1b GEMM: weight rows 176.., RT=4 over 32 rows, accumulates into evt.
__device__ __forceinline__ void gemm_event_b(
    float* __restrict__ Abuf, const EventGenB& gen,
    float* __restrict__ C, int tid)
{
    const int ty = tid >> 5, tx = tid & 31;
    ull acc[4][3];
#pragma unroll
    for (int i = 0; i < 4; i++)
#pragma unroll
        for (int g = 0; g < 3; g++) acc[i][g] = 0ull;

    gen(Abuf, 0, tid);
    __syncthreads();
#pragma unroll 1
    for (int kc = 0; kc < 176; kc += 44) {
        int buf = (kc / 44) & 1;
        const float* cur = Abuf + buf*2112;
        if (kc + 44 < 176) gen(Abuf + (buf^1)*2112, kc + 44, tid);
        const float* wq   = g_WT_event + (176 + kc)*192 + 2*tx;
        const float* arow = cur + ty*4*44;
#pragma unroll 1
        for (int k4 = 0; k4 < 44; k4 += 4) {
            float4 av[4];
#pragma unroll
            for (int i = 0; i < 4; i++)
                av[i] = *reinterpret_cast<const float4*>(arow + i*44 + k4);
#pragma unroll
            for (int kk = 0; kk < 4; kk++) {
                ull w[3];
#pragma unroll
                for (int g = 0; g < 3; g++)
                    w[g] = __ldg(reinterpret_cast<const ull*>(wq + (k4+kk)*192 + g*64));
#pragma unroll
                for (int i = 0; i < 4; i++) {
                    float a = fsel4(av[i], kk);
                    ull ad = pack2(a, a);
#pragma unroll
                    for (int g = 0; g < 3; g++) fma2(acc[i][g], ad, w[g]);
                }
            }
        }
        __syncthreads();
    }
#pragma unroll
    for (int i = 0; i < 4; i++)
#pragma unroll
        for (int g = 0; g < 3; g++) {
            int col = g*64 + 2*tx;
            float x, y; unpack2(acc[i][g], x, y);
            int rr = ty*4 + i;
            int row = (rr >> 1)*3 + (rr & 1);
            if (col < 172)     C[row*176 + col]     += x;
            if (col + 1 < 172) C[row*176 + col + 1] += y;
        }
}

// ---------------------------------------------------------------------------
// Dual gine: double-buffered gen (KC=16, 11 chunks).
// Abuf layout: 2 buffers x (2 images x 48x16 = 1536) = 3072 floats.
// ---------------------------------------------------------------------------
struct GineDualGen {
    const int*   sNS;
    const int*   sNT;
    const float* node_embed;
    const float* evt;   // smem, pitch 176
    __device__ __forceinline__ void operator()(float* buf, int kc, int tid) const {
        for (int idx = tid; idx < ROWS*16; idx += NTHREADS) {
            int r = idx >> 4, cc = idx & 15;
            int c = kc + cc;
            float v1 = 0.f, v2 = 0.f;
            if (c < 172) {
                float s = __ldg(&node_embed[(long)sNS[r]*172 + c]);
                float t = __ldg(&node_embed[(long)sNT[r]*172 + c]);
                float e = evt[r*176 + c];
                v1 = s + fmaxf(t + e, 0.f);
                v2 = t + fmaxf(s + e, 0.f);
            }
            buf[idx]       = v1;
            buf[768 + idx] = v2;
        }
    }
};

__device__ __forceinline__ void gemm_gine_dual(
    const float* __restrict__ bias,
    float* __restrict__ Abuf, const GineDualGen& gen,
    float* __restrict__ C1, float* __restrict__ C2, int tid)
{
    const int ty = tid >> 5, tx = tid & 31;
    ull acc1[6], acc2[6];
#pragma unroll
    for (int i = 0; i < 6; i++) { acc1[i] = 0ull; acc2[i] = 0ull; }

    gen(Abuf, 0, tid);
    __syncthreads();
#pragma unroll 1
    for (int kc = 0; kc < 176; kc += 16) {
        int buf = (kc >> 4) & 1;
        const float* cur = Abuf + buf*1536;
        if (kc + 16 < 176) gen(Abuf + (buf^1)*1536, kc + 16, tid);
        const float* wq = g_WT_gcn1 + kc*64 + 2*tx;
        const float* a1row = cur + ty*6*16;
        const float* a2row = cur + 768 + ty*6*16;
#pragma unroll 1
        for (int k4 = 0; k4 < 16; k4 += 4) {
            ull w[4];
#pragma unroll
            for (int kk = 0; kk < 4; kk++)
                w[kk] = __ldg(reinterpret_cast<const ull*>(wq + (k4+kk)*64));
#pragma unroll
            for (int i = 0; i < 6; i++) {
                float4 a1 = *reinterpret_cast<const float4*>(a1row + i*16 + k4);
                float4 a2 = *reinterpret_cast<const float4*>(a2row + i*16 + k4);
#pragma unroll
                for (int kk = 0; kk < 4; kk++) {
                    fma2(acc1[i], pack2(fsel4(a1,kk), fsel4(a1,kk)), w[kk]);
                    fma2(acc2[i], pack2(fsel4(a2,kk), fsel4(a2,kk)), w[kk]);
                }
            }
        }
        __syncthreads();
    }
    int col = 2*tx;
    float b0 = __ldg(&bias[col]), b1 = __ldg(&bias[col+1]);
#pragma unroll
    for (int i = 0; i < 6; i++) {
        int row = ty*6 + i;
        float x, y;
        unpack2(acc1[i], x, y);
        C1[row*64 + col]     = fmaxf(x + b0, 0.f);
        C1[row*64 + col + 1] = fmaxf(y + b1, 0.f);
        unpack2(acc2[i], x, y);
        C2[row*64 + col]     = fmaxf(x + b0, 0.f);
        C2[row*64 + col + 1] = fmaxf(y + b1, 0.f);
    }
    __syncthreads();
}

__device__ __forceinline__ void gemm_gcn2_dual(
    const float* __restrict__ bias,
    const float* __restrict__ H1, const float* __restrict__ H2,
    float* __restrict__ feat, int tid)
{
    const int ty = tid >> 5, tx = tid & 31;
    ull acc1[6], acc2[6];
#pragma unroll
    for (int i = 0; i < 6; i++) { acc1[i] = 0ull; acc2[i] = 0ull; }
    const float* wq = g_WT_gcn2 + 2*tx;
#pragma unroll 1
    for (int k4 = 0; k4 < 64; k4 += 4) {
        ull w[4];
#pragma unroll
        for (int kk = 0; kk < 4; kk++)
            w[kk] = __ldg(reinterpret_cast<const ull*>(wq + (k4+kk)*64));
#pragma unroll
        for (int i = 0; i < 6; i++) {
            float4 a1 = *reinterpret_cast<const float4*>(H1 + (ty*6+i)*64 + k4);
            float4 a2 = *reinterpret_cast<const float4*>(H2 + (ty*6+i)*64 + k4);
#pragma unroll
            for (int kk = 0; kk < 4; kk++) {
                fma2(acc1[i], pack2(fsel4(a1,kk), fsel4(a1,kk)), w[kk]);
                fma2(acc2[i], pack2(fsel4(a2,kk), fsel4(a2,kk)), w[kk]);
            }
        }
    }
    __syncthreads();
    int col = 2*tx;
    float b0 = __ldg(&bias[col]), b1 = __ldg(&bias[col+1]);
#pragma unroll
    for (int i = 0; i < 6; i++) {
        int row = ty*6 + i;
        float x, y;
        unpack2(acc1[i], x, y);
        feat[row*128 + col]      = x + b0;
        feat[row*128 + col + 1]  = y + b1;
        unpack2(acc2[i], x, y);
        feat[row*128 + 64 + col]     = x + b0;
        feat[row*128 + 64 + col + 1] = y + b1;
    }
    __syncthreads();
}

// ---------------------------------------------------------------------------
// Fused main kernel
// ---------------------------------------------------------------------------
__global__ void __launch_bounds__(NTHREADS, 3)
fused_kernel(const int*   __restrict__ node_idx,
             const int*   __restrict__ edge_idx,
             const int*   __restrict__ cat_feat,
             const float* __restrict__ t_records,
             const float* __restrict__ edge_identify,
             const float* __restrict__ node_embed,
             const float* __restrict__ edge_embed,
             const float* __restrict__ basis_freq,
             const float* __restrict__ phase,
             const float* __restrict__ lin_event_b,
             const float* __restrict__ gcn_b1,
             const float* __restrict__ gcn_b2,
             const float* __restrict__ att_w1_b,
             const float* __restrict__ att_w2_b,
             const float* __restrict__ att_m1_b,
             const float* __restrict__ att_m2_b,
             const float* __restrict__ mlp_b1,
             const float* __restrict__ mlp_b2,
             const float* __restrict__ mlp_w3,
             const float* __restrict__ mlp_b3,
             float*       __restrict__ out)
{
    extern __shared__ float sm[];
    const int tid = threadIdx.x;
    const int g0  = blockIdx.x * PAIRS;

    float* evt  = sm + EVT_OFF;
    float* feat = sm + FEAT_OFF;
    float* Abuf = sm + ABUF_OFF;
    int*   sNS  = reinterpret_cast<int*>(sm + SG_OFF);
    int*   sNT  = sNS + 48;
    int*   sE   = sNS + 96;
    float* sDT  = sm + SG_OFF + 144;

    // ---- Phase 0: stage indices + dt ----
    if (tid < ROWS) {
        int p = tid / 3, l = tid - p*3;
        int g = g0 + p;
        sNS[tid] = __ldg(&node_idx[g*6 + 2*l]);
        sNT[tid] = __ldg(&node_idx[g*6 + 2*l + 1]);
        sE[tid]  = __ldg(&edge_idx[g*3 + l]);
        sDT[tid] = __ldg(&t_records[g*3 + 2]) - __ldg(&t_records[g*3 + l]);
    }
    __syncthreads();

    // ---- Phase 1a/1b/1c: event linear ----
    EventGenA ega{sE, sDT, edge_embed, edge_identify, basis_freq, phase, g0};
    gemm_event_a(lin_event_b, Abuf, ega, evt, tid);
    EventGenB egb{sDT, basis_freq, phase};
    gemm_event_b(Abuf, egb, evt, tid);
    for (int idx = tid; idx < PAIRS*172; idx += NTHREADS) {
        int p = idx / 172, c = idx - p*172;
        evt[(p*3 + 2)*176 + c] += __ldg(&g_ct2[c]);
    }
    __syncthreads();   // gine's first gen reads evt immediately

    // ---- Phase 2/3: dual gine (double-buffered gen) + dual gcn2 ----
    GineDualGen gg{sNS, sNT, node_embed, evt};
    gemm_gine_dual(gcn_b1, Abuf, gg, sm + GH1_OFF, sm + GH2_OFF, tid);
    gemm_gcn2_dual(gcn_b2, sm + GH1_OFF, sm + GH2_OFF, feat, tid);

    // ---- Phase 4: attention (k-split GEMMs, row-mapped A) ----
    float* Wq = sm + WQ_OFF;
    gemm_ksplit<128,128,64,8,4,2,false,128,128>(g_WT_att2, att_w2_b,
                                                TgtMap{feat}, Wq, 128, tid);
    float* Wp = sm + WP_OFF;
    gemm_ksplit<128,128,64,4,4,2,false,128,128>(g_WT_att1, att_w1_b,
                                                SrcMap{feat}, Wp, 128, tid);

    float* scb = sm + SC_OFF;
    {
        int pk = tid >> 3, sub = tid & 7;
        int p = pk >> 1, k = pk & 1;
        float s = 0.f;
        for (int j = sub; j < 128; j += 8)
            s += Wp[p*128 + j] * Wq[(2*p + k)*128 + j];
        s += __shfl_down_sync(0xffffffffu, s, 4, 8);
        s += __shfl_down_sync(0xffffffffu, s, 2, 8);
        s += __shfl_down_sync(0xffffffffu, s, 1, 8);
        if (sub == 0) scb[pk] = s;
    }
    __syncthreads();
    float* outb = sm + OUTB_OFF;
    for (int idx = tid; idx < PAIRS*128; idx += NTHREADS) {
        int p = idx >> 7, c = idx & 127;
        float s0 = scb[2*p], s1 = scb[2*p + 1];
        float m = fmaxf(s0, s1);
        float e0 = __expf(s0 - m), e1 = __expf(s1 - m);
        float inv = 1.f / (e0 + e1);
        outb[idx] = feat[(p*3 + 2)*128 + c]
                  + (e0*inv) * Wq[(2*p)*128 + c]
                  + (e1*inv) * Wq[(2*p + 1)*128 + c];
    }
    __syncthreads();

    float* hb = sm + HB_OFF;
    float* sf = sm + SF_OFF;
    gemm_ksplit<64,128,64,4,4,1,true,64,64>(g_WT_m1, att_m1_b,
                                            PitchMap{outb,128}, hb, 64, tid);
    gemm_ksplit<64,64,32,4,4,1,false,64,64>(g_WT_m2, att_m2_b,
                                            PitchMap{hb,64}, sf, 64, tid);

    // ---- Phase 5: MLP tail (k-split GEMMs, K padded to 80) ----
    float* xb  = sm + XB_OFF;
    float* h1b = sm + H1_OFF;
    float* h2b = sm + H2_OFF;
    for (int idx = tid; idx < PAIRS*80; idx += NTHREADS) {
        int p = idx / 80, c = idx - p*80;
        float v = 0.f;
        if (c < 64)      v = sf[p*64 + c];
        else if (c < 76) v = (__ldg(&cat_feat[g0 + p]) == (c - 64)) ? 1.f : 0.f;
        xb[idx] = v;
    }
    __syncthreads();
    gemm_ksplit<128,80,40,4,4,2,true,76,80>(g_WT_mlp1, mlp_b1,
                                            PitchMap{xb,80}, h1b, 80, tid);
    gemm_ksplit<64,80,40,4,4,1,true,64,64>(g_WT_mlp2, mlp_b2,
                                           PitchMap{h1b,80}, h2b, 64, tid);

    if (tid < PAIRS) {
        float z = __ldg(&mlp_b3[0]);
        const float* x = h2b + tid*64;
#pragma unroll 4
        for (int k = 0; k < 64; k++) z += x[k] * __ldg(&mlp_w3[k]);
        out[g0 + tid] = 1.f / (1.f + __expf(-z));
    }
}

// ---------------------------------------------------------------------------
// Launch
// ---------------------------------------------------------------------------
extern "C" void kernel_launch(void* const* d_in, const int* in_sizes, int n_in,
                              void* d_out, int out_size)
{
    const int*   node_idx      = (const int*)  d_in[0];
    const int*   edge_idx      = (const int*)  d_in[1];
    const int*   cat_feat      = (const int*)  d_in[2];
    const float* t_records     = (const float*)d_in[3];
    const float* edge_identify = (const float*)d_in[4];
    // d_in[5] = cut_time_l (unused by reference)
    const float* node_embed    = (const float*)d_in[6];
    const float* edge_embed    = (const float*)d_in[7];
    const float* basis_freq    = (const float*)d_in[8];
    const float* phase         = (const float*)d_in[9];
    const float* lin_event_w   = (const float*)d_in[10];
    const float* lin_event_b   = (const float*)d_in[11];
    const float* gcn_w1        = (const float*)d_in[12];
    const float* gcn_b1        = (const float*)d_in[13];
    const float* gcn_w2        = (const float*)d_in[14];
    const float* gcn_b2        = (const float*)d_in[15];
    const float* att_w1_w      = (const float*)d_in[16];
    const float* att_w1_b      = (const float*)d_in[17];
    const float* att_w2_w      = (const float*)d_in[18];
    const float* att_w2_b      = (const float*)d_in[19];
    const float* att_m1_w      = (const float*)d_in[20];
    const float* att_m1_b      = (const float*)d_in[21];
    const float* att_m2_w      = (const float*)d_in[22];
    const float* att_m2_b      = (const float*)d_in[23];
    const float* mlp_w1        = (const float*)d_in[24];
    const float* mlp_b1        = (const float*)d_in[25];
    const float* mlp_w2        = (const float*)d_in[26];
    const float* mlp_b2        = (const float*)d_in[27];
    const float* mlp_w3        = (const float*)d_in[28];
    const float* mlp_b3        = (const float*)d_in[29];
    float* outp = (float*)d_out;

    cudaFuncSetAttribute(fused_kernel,
                         cudaFuncAttributeMaxDynamicSharedMemorySize, SMEM_BYTES);

    prep_kernel<<<128, 256>>>(lin_event_w, gcn_w1, gcn_w2,
                              att_w1_w, att_w2_w, att_m1_w, att_m2_w,
                              mlp_w1, mlp_w2, phase);

    fused_kernel<<<NBLK, NTHREADS, SMEM_BYTES>>>(
        node_idx, edge_idx, cat_feat, t_records, edge_identify,
        node_embed, edge_embed, basis_freq, phase,
        lin_event_b, gcn_b1, gcn_b2,
        att_w1_b, att_w2_b, att_m1_b, att_m2_b,
        mlp_b1, mlp_b2, mlp_w3, mlp_b3,
        outp);
}